// round 1
// baseline (speedup 1.0000x reference)
#include <cuda_runtime.h>
#include <math.h>

#define B_  8
#define S_  1024
#define D_  1024
#define H_  16
#define E_  64
#define HE_ 1024
#define BS_ (B_*S_)
#define NT_ (S_/64)   // 16 tiles of 64 along seq

// ---------------- scratch (device globals; no runtime allocation) ----------
__device__ float g_Q [B_*S_*HE_];                 // [B,S,H*E]
__device__ float g_K [B_*S_*HE_];
__device__ float g_V [B_*S_*HE_];
__device__ float g_AO[B_*S_*HE_];                 // attention output, combined heads
__device__ float g_Sc[(size_t)B_*H_*S_*S_];       // scores/attn [B*H, Sq, Sk] (lower tiles only)
__device__ float g_TS[B_*H_*NT_*E_];              // per-64-tile V sums
__device__ float g_P [B_*H_*(NT_+1)*E_];          // prefix sums at tile boundaries

// ---------------- dense GEMM: C[M,N] = A[M,K] @ W[K,N] + bias --------------
// 128x128 tile, BK=16, 256 threads, 8x8 microtile
__global__ __launch_bounds__(256) void gemm_bias_kernel(
    const float* __restrict__ A, const float* __restrict__ W,
    const float* __restrict__ bias, float* __restrict__ C,
    int M, int N, int K)
{
    __shared__ float AsT[16][132];   // transposed A tile, padded
    __shared__ float Bs [16][128];

    const int t  = threadIdx.x;
    const int tx = t & 15, ty = t >> 4;
    const int bm = blockIdx.y, bn = blockIdx.x;
    const int rm = ty * 8, cn = tx * 8;

    float acc[8][8];
    #pragma unroll
    for (int i = 0; i < 8; i++)
        #pragma unroll
        for (int j = 0; j < 8; j++) acc[i][j] = 0.f;

    const int ar = t >> 2, av = t & 3;     // A loader: 2 float4 (rows ar, ar+64)
    const int br = t >> 5, bv = t & 31;    // B loader: 2 float4 (rows br, br+8)
    const float* Aptr = A + (size_t)(bm*128 + ar) * K + av * 4;
    const float* Wptr = W + (size_t)br * N + bn*128 + bv * 4;

    for (int kt = 0; kt < K; kt += 16) {
        float4 a0 = *(const float4*)(Aptr + kt);
        float4 a1 = *(const float4*)(Aptr + (size_t)64 * K + kt);
        float4 b0 = *(const float4*)(Wptr + (size_t)kt * N);
        float4 b1 = *(const float4*)(Wptr + (size_t)(kt + 8) * N);
        __syncthreads();
        AsT[av*4+0][ar]    = a0.x; AsT[av*4+1][ar]    = a0.y;
        AsT[av*4+2][ar]    = a0.z; AsT[av*4+3][ar]    = a0.w;
        AsT[av*4+0][ar+64] = a1.x; AsT[av*4+1][ar+64] = a1.y;
        AsT[av*4+2][ar+64] = a1.z; AsT[av*4+3][ar+64] = a1.w;
        *(float4*)&Bs[br  ][bv*4] = b0;
        *(float4*)&Bs[br+8][bv*4] = b1;
        __syncthreads();
        #pragma unroll
        for (int kk = 0; kk < 16; kk++) {
            float a[8], b[8];
            *(float4*)(a)     = *(const float4*)&AsT[kk][rm];
            *(float4*)(a + 4) = *(const float4*)&AsT[kk][rm + 4];
            *(float4*)(b)     = *(const float4*)&Bs [kk][cn];
            *(float4*)(b + 4) = *(const float4*)&Bs [kk][cn + 4];
            #pragma unroll
            for (int i = 0; i < 8; i++)
                #pragma unroll
                for (int j = 0; j < 8; j++) acc[i][j] = fmaf(a[i], b[j], acc[i][j]);
        }
    }

    float bfrag[8];
    #pragma unroll
    for (int j = 0; j < 8; j++) bfrag[j] = bias[bn*128 + cn + j];
    #pragma unroll
    for (int i = 0; i < 8; i++) {
        const size_t row = (size_t)(bm*128 + rm + i);
        float4 v0, v1;
        v0.x = acc[i][0] + bfrag[0]; v0.y = acc[i][1] + bfrag[1];
        v0.z = acc[i][2] + bfrag[2]; v0.w = acc[i][3] + bfrag[3];
        v1.x = acc[i][4] + bfrag[4]; v1.y = acc[i][5] + bfrag[5];
        v1.z = acc[i][6] + bfrag[6]; v1.w = acc[i][7] + bfrag[7];
        *(float4*)&C[row * N + bn*128 + cn]     = v0;
        *(float4*)&C[row * N + bn*128 + cn + 4] = v1;
    }
}

// ---------------- scores: S[bh,q,k] = (Q·K)/sqrt(8), causal tiles only -----
// mask (k>q) -> -1e9; exact-zero quirk -> -1e9
__global__ __launch_bounds__(256) void scores_kernel()
{
    const int kt = blockIdx.x, qt = blockIdx.y;
    if (kt > qt) return;
    const int bh = blockIdx.z;
    const int b = bh >> 4, h = bh & 15;

    __shared__ float Qs[64][65];
    __shared__ float Ks[64][65];
    const int t = threadIdx.x;

    const float* Qbase = g_Q + ((size_t)(b*S_ + qt*64)) * HE_ + h*64;
    const float* Kbase = g_K + ((size_t)(b*S_ + kt*64)) * HE_ + h*64;
    #pragma unroll
    for (int idx = t; idx < 4096; idx += 256) {
        const int r = idx >> 6, e = idx & 63;
        Qs[r][e] = Qbase[(size_t)r * HE_ + e];
        Ks[r][e] = Kbase[(size_t)r * HE_ + e];
    }
    __syncthreads();

    const int tx = t & 15, ty = t >> 4;
    const int r0 = ty * 4, c0 = tx * 4;
    float acc[4][4];
    #pragma unroll
    for (int i = 0; i < 4; i++)
        #pragma unroll
        for (int j = 0; j < 4; j++) acc[i][j] = 0.f;

    #pragma unroll 8
    for (int e = 0; e < 64; e++) {
        float a[4], bb[4];
        #pragma unroll
        for (int i = 0; i < 4; i++) a[i]  = Qs[r0 + i][e];
        #pragma unroll
        for (int j = 0; j < 4; j++) bb[j] = Ks[c0 + j][e];
        #pragma unroll
        for (int i = 0; i < 4; i++)
            #pragma unroll
            for (int j = 0; j < 4; j++) acc[i][j] = fmaf(a[i], bb[j], acc[i][j]);
    }

    const float scale = 0.35355339059327373f; // 1/sqrt(8) — batch-size quirk
    float* out = g_Sc + ((size_t)bh * S_ + qt*64) * S_ + kt*64;
    #pragma unroll
    for (int i = 0; i < 4; i++) {
        const int qg = qt*64 + r0 + i;
        #pragma unroll
        for (int j = 0; j < 4; j++) {
            const int kg = kt*64 + c0 + j;
            float v = acc[i][j] * scale;
            if (kg > qg || v == 0.0f) v = -1e9f;
            out[(size_t)(r0 + i) * S_ + (c0 + j)] = v;
        }
    }
}

// ---------------- softmax over HEADS axis (the dim=1 quirk), in place ------
__global__ void softmax_h_kernel()
{
    const int k = blockIdx.x * 256 + threadIdx.x;
    const int q = blockIdx.y;
    const int b = blockIdx.z;
    const int kmax = ((q >> 6) + 1) << 6;   // only causal tiles were written
    if (k >= kmax) return;

    const size_t base = (size_t)b * H_ * S_ * S_ + (size_t)q * S_ + k;
    const size_t hs   = (size_t)S_ * S_;
    float s[H_];
    float m = -3.4e38f;
    #pragma unroll
    for (int h = 0; h < H_; h++) { s[h] = g_Sc[base + h * hs]; m = fmaxf(m, s[h]); }
    float Z = 0.f;
    #pragma unroll
    for (int h = 0; h < H_; h++) { s[h] = expf(s[h] - m); Z += s[h]; }
    const float inv = 1.0f / Z;
    #pragma unroll
    for (int h = 0; h < H_; h++) g_Sc[base + h * hs] = s[h] * inv;
}

// ---------------- V tile sums + boundary prefix scan -----------------------
__global__ void tilesum_kernel()   // grid: B*H*NT_, block: 64
{
    const int blk = blockIdx.x;
    const int e = threadIdx.x;
    const int tt = blk & (NT_ - 1);
    const int bh = blk / NT_;
    const int b = bh >> 4, h = bh & 15;
    const float* Vb = g_V + ((size_t)(b*S_ + tt*64)) * HE_ + h*64 + e;
    float sum = 0.f;
    #pragma unroll 8
    for (int k = 0; k < 64; k++) sum += Vb[(size_t)k * HE_];
    g_TS[((size_t)bh * NT_ + tt) * E_ + e] = sum;
}

__global__ void scan_kernel()      // 8192 threads total
{
    const int id = blockIdx.x * 256 + threadIdx.x;
    const int e = id & 63, bh = id >> 6;
    float* P = g_P + (size_t)bh * (NT_ + 1) * E_;
    float p = 0.f;
    P[e] = 0.f;
    #pragma unroll
    for (int tt = 0; tt < NT_; tt++) {
        p += g_TS[((size_t)bh * NT_ + tt) * E_ + e];
        P[(tt + 1) * E_ + e] = p;
    }
}

// ---------------- out = attn @ V (causal) + (1/16)*suffix(V) ---------------
__global__ __launch_bounds__(256) void attnv_kernel()  // grid (qt, h, b)
{
    const int qt = blockIdx.x, h = blockIdx.y, b = blockIdx.z;
    const int bh = b * H_ + h;

    __shared__ float As[64][65];
    __shared__ float Vs[64][65];
    const int t = threadIdx.x;
    const int tx = t & 15, ty = t >> 4;
    const int r0 = ty * 4, c0 = tx * 4;

    float acc[4][4];
    #pragma unroll
    for (int i = 0; i < 4; i++)
        #pragma unroll
        for (int j = 0; j < 4; j++) acc[i][j] = 0.f;

    const float* Sbase = g_Sc + ((size_t)bh * S_ + qt*64) * S_;
    for (int kt = 0; kt <= qt; kt++) {
        __syncthreads();
        #pragma unroll
        for (int idx = t; idx < 4096; idx += 256) {
            const int r = idx >> 6, c = idx & 63;
            As[r][c] = Sbase[(size_t)r * S_ + kt*64 + c];
            Vs[r][c] = g_V[((size_t)(b*S_ + kt*64 + r)) * HE_ + h*64 + c];
        }
        __syncthreads();
        #pragma unroll 8
        for (int k = 0; k < 64; k++) {
            float a[4], vv[4];
            #pragma unroll
            for (int i = 0; i < 4; i++) a[i]  = As[r0 + i][k];
            #pragma unroll
            for (int j = 0; j < 4; j++) vv[j] = Vs[k][c0 + j];
            #pragma unroll
            for (int i = 0; i < 4; i++)
                #pragma unroll
                for (int j = 0; j < 4; j++) acc[i][j] = fmaf(a[i], vv[j], acc[i][j]);
        }
    }

    // masked region (k beyond qt tile): every head gets attn = 1/16 exactly
    const float* P = g_P + (size_t)bh * (NT_ + 1) * E_;
    float suf[4];
    #pragma unroll
    for (int j = 0; j < 4; j++)
        suf[j] = (P[NT_ * E_ + c0 + j] - P[(qt + 1) * E_ + c0 + j]) * 0.0625f;

    #pragma unroll
    for (int i = 0; i < 4; i++) {
        const size_t row = (size_t)(b*S_ + qt*64 + r0 + i);
        #pragma unroll
        for (int j = 0; j < 4; j++)
            g_AO[row * HE_ + h*64 + c0 + j] = acc[i][j] + suf[j];
    }
}

// ---------------- launch ---------------------------------------------------
extern "C" void kernel_launch(void* const* d_in, const int* in_sizes, int n_in,
                              void* d_out, int out_size)
{
    const float* X1 = (const float*)d_in[0];
    const float* X2 = (const float*)d_in[1];
    const float* Wq = (const float*)d_in[2];
    const float* bq = (const float*)d_in[3];
    const float* Wk = (const float*)d_in[4];
    const float* bk = (const float*)d_in[5];
    const float* Wv = (const float*)d_in[6];
    const float* bv = (const float*)d_in[7];
    const float* Wo = (const float*)d_in[8];
    const float* bo = (const float*)d_in[9];
    float* out = (float*)d_out;

    void *pQ, *pK, *pV, *pAO;
    cudaGetSymbolAddress(&pQ,  g_Q);
    cudaGetSymbolAddress(&pK,  g_K);
    cudaGetSymbolAddress(&pV,  g_V);
    cudaGetSymbolAddress(&pAO, g_AO);

    const dim3 gGemm(HE_ / 128, BS_ / 128);   // (8, 64)

    // Q/K/V projections
    gemm_bias_kernel<<<gGemm, 256>>>(X1, Wq, bq, (float*)pQ, BS_, HE_, D_);
    gemm_bias_kernel<<<gGemm, 256>>>(X2, Wk, bk, (float*)pK, BS_, HE_, D_);
    gemm_bias_kernel<<<gGemm, 256>>>(X2, Wv, bv, (float*)pV, BS_, HE_, D_);

    // V suffix machinery for the all-masked (attn = 1/16) region
    tilesum_kernel<<<B_ * H_ * NT_, 64>>>();
    scan_kernel<<<(B_ * H_ * E_) / 256, 256>>>();

    // causal score tiles with mask + exact-zero quirk
    scores_kernel<<<dim3(NT_, NT_, B_ * H_), 256>>>();

    // softmax across the 16 heads (legacy dim=1 quirk)
    softmax_h_kernel<<<dim3(S_ / 256, S_, B_), 256>>>();

    // attn @ V + analytic masked suffix
    attnv_kernel<<<dim3(NT_, H_, B_), 256>>>();

    // output projection straight into d_out
    gemm_bias_kernel<<<gGemm, 256>>>((const float*)pAO, Wo, bo, out, BS_, HE_, D_);
}

// round 3
// speedup vs baseline: 1.3500x; 1.3500x over previous
#include <cuda_runtime.h>
#include <cuda_bf16.h>
#include <cstdint>
#include <math.h>

#define B_  8
#define S_  1024
#define D_  1024
#define H_  16
#define E_  64
#define HE_ 1024
#define BS_ (B_*S_)
#define NT_ (S_/64)
#define KP_ 3072          // packed K: [hi | lo | hi] x [hi | hi | lo]

// ---------------- scratch (device globals; no runtime allocation) ----------
__device__ float g_Q [B_*S_*HE_];
__device__ float g_K [B_*S_*HE_];
__device__ float g_V [B_*S_*HE_];
__device__ float g_AO[B_*S_*HE_];
__device__ float g_Sc[(size_t)B_*H_*S_*S_];
__device__ float g_TS[B_*H_*NT_*E_];
__device__ float g_P [B_*H_*(NT_+1)*E_];

// packed bf16 operands (K folded x3)
__device__ __nv_bfloat16 g_X1p[(size_t)BS_*KP_];
__device__ __nv_bfloat16 g_X2p[(size_t)BS_*KP_];
__device__ __nv_bfloat16 g_AOp[(size_t)BS_*KP_];
__device__ __nv_bfloat16 g_Wqp[(size_t)HE_*KP_];   // [N=1024, KP] K-major
__device__ __nv_bfloat16 g_Wkp[(size_t)HE_*KP_];
__device__ __nv_bfloat16 g_Wvp[(size_t)HE_*KP_];
__device__ __nv_bfloat16 g_Wop[(size_t)HE_*KP_];

// ---------------- PTX helpers (all baseline sm_80+; safe for sm_103) -------
__device__ __forceinline__ uint32_t smem_u32(const void* p) {
    uint32_t a;
    asm("{ .reg .u64 t; cvta.to.shared.u64 t, %1; cvt.u32.u64 %0, t; }" : "=r"(a) : "l"(p));
    return a;
}
__device__ __forceinline__ void cp16(uint32_t s, const void* g) {
    asm volatile("cp.async.cg.shared.global [%0], [%1], 16;" :: "r"(s), "l"(g));
}
#define CP_COMMIT() asm volatile("cp.async.commit_group;" ::: "memory")
#define CP_WAIT1()  asm volatile("cp.async.wait_group 1;" ::: "memory")
#define CP_WAIT0()  asm volatile("cp.async.wait_group 0;" ::: "memory")

#define LDSM4(r, a) \
    asm volatile("ldmatrix.sync.aligned.m8n8.x4.shared.b16 {%0,%1,%2,%3}, [%4];" \
        : "=r"((r)[0]), "=r"((r)[1]), "=r"((r)[2]), "=r"((r)[3]) : "r"(a))

#define MMA16816(c, a, b0v, b1v) \
    asm volatile("mma.sync.aligned.m16n8k16.row.col.f32.bf16.bf16.f32 " \
        "{%0,%1,%2,%3}, {%4,%5,%6,%7}, {%8,%9}, {%0,%1,%2,%3};" \
        : "+f"((c)[0]), "+f"((c)[1]), "+f"((c)[2]), "+f"((c)[3]) \
        : "r"((a)[0]), "r"((a)[1]), "r"((a)[2]), "r"((a)[3]), "r"(b0v), "r"(b1v))

// ---------------- pack kernels ---------------------------------------------
// X fp32 [R,1024] -> bf16 [R,3072] as [hi | lo | hi]
__global__ __launch_bounds__(256) void pack_x_kernel(
    const float* __restrict__ in, __nv_bfloat16* __restrict__ out, int n4)
{
    int i = blockIdx.x * 256 + threadIdx.x;
    if (i >= n4) return;
    const int row = i >> 8;
    const int c   = (i & 255) * 4;
    float4 v = ((const float4*)in)[i];
    float f[4] = {v.x, v.y, v.z, v.w};
    __nv_bfloat162 h2[2], l2[2];
    #pragma unroll
    for (int j = 0; j < 2; j++) {
        __nv_bfloat16 h0 = __float2bfloat16_rn(f[2*j]);
        __nv_bfloat16 h1 = __float2bfloat16_rn(f[2*j+1]);
        __nv_bfloat16 l0 = __float2bfloat16_rn(f[2*j]   - __bfloat162float(h0));
        __nv_bfloat16 l1 = __float2bfloat16_rn(f[2*j+1] - __bfloat162float(h1));
        h2[j] = __nv_bfloat162(h0, h1);
        l2[j] = __nv_bfloat162(l0, l1);
    }
    __nv_bfloat16* base = out + (size_t)row * KP_;
    *(__nv_bfloat162*)(base + c)          = h2[0];
    *(__nv_bfloat162*)(base + c + 2)      = h2[1];
    *(__nv_bfloat162*)(base + 1024 + c)   = l2[0];
    *(__nv_bfloat162*)(base + 1024 + c+2) = l2[1];
    *(__nv_bfloat162*)(base + 2048 + c)   = h2[0];
    *(__nv_bfloat162*)(base + 2048 + c+2) = h2[1];
}

// W fp32 [K=1024, N=1024] -> Wt bf16 [N, 3072] as [hi | hi | lo]
__global__ __launch_bounds__(256) void pack_w_kernel(
    const float* __restrict__ W, __nv_bfloat16* __restrict__ out)
{
    __shared__ float t[32][33];
    const int n0 = blockIdx.x * 32, k0 = blockIdx.y * 32;
    const int tx = threadIdx.x, ty = threadIdx.y;
    #pragma unroll
    for (int i = 0; i < 4; i++)
        t[ty + i*8][tx] = W[(size_t)(k0 + ty + i*8) * 1024 + n0 + tx];
    __syncthreads();
    #pragma unroll
    for (int i = 0; i < 4; i++) {
        float v = t[tx][ty + i*8];
        __nv_bfloat16 h = __float2bfloat16_rn(v);
        __nv_bfloat16 l = __float2bfloat16_rn(v - __bfloat162float(h));
        size_t o = (size_t)(n0 + ty + i*8) * KP_ + k0 + tx;
        out[o]        = h;
        out[o + 1024] = h;
        out[o + 2048] = l;
    }
}

// ---------------- mma.sync bf16 GEMM: C[8192,1024] = A' Bt'^T + bias -------
// A' [8192, 3072] K-major, B' [1024, 3072] K-major.
// CTA 128x128, BK=32, 3-stage cp.async pipeline, 8 warps (2m x 4n), warp 64x32.
// smem rows padded to 80B (conflict-free ldmatrix). Stage = 20480B, total 61440B.
__global__ __launch_bounds__(256) void gemm_mma_kernel(
    const __nv_bfloat16* __restrict__ Ap, const __nv_bfloat16* __restrict__ Bp,
    const float* __restrict__ bias, float* __restrict__ C)
{
    extern __shared__ char smch[];
    const uint32_t sb = smem_u32(smch);
    const int tid = threadIdx.x;
    const int lane = tid & 31, wid = tid >> 5;
    const int wm = wid >> 2, wn = wid & 3;
    const size_t m0 = (size_t)blockIdx.y * 128;
    const size_t n0 = (size_t)blockIdx.x * 128;

    // loader: thread -> (row = tid>>2 in [0,64), 16B chunk = tid&3); 2 rows each for A and B
    const int lr = tid >> 2;
    const int lco = (tid & 3) * 16;
    const __nv_bfloat16* gA0 = Ap + (m0 + lr) * KP_ + (tid & 3) * 8;
    const __nv_bfloat16* gB0 = Bp + (n0 + lr) * KP_ + (tid & 3) * 8;
    const uint32_t smA = sb + lr * 80 + lco;
    const uint32_t smB = smA + 10240;

    float acc[4][4][4];
    #pragma unroll
    for (int a = 0; a < 4; a++)
        #pragma unroll
        for (int b = 0; b < 4; b++)
            #pragma unroll
            for (int c = 0; c < 4; c++) acc[a][b][c] = 0.f;

    #define LOADST(kt, st) do {                                        \
        const uint32_t so_ = (uint32_t)(st) * 20480u;                  \
        const __nv_bfloat16* ga_ = gA0 + (kt) * 32;                    \
        const __nv_bfloat16* gb_ = gB0 + (kt) * 32;                    \
        cp16(smA + so_,           ga_);                                \
        cp16(smA + so_ + 64*80,   ga_ + (size_t)64 * KP_);             \
        cp16(smB + so_,           gb_);                                \
        cp16(smB + so_ + 64*80,   gb_ + (size_t)64 * KP_);             \
        CP_COMMIT();                                                   \
    } while (0)

    LOADST(0, 0);
    LOADST(1, 1);

    // ldmatrix lane addresses (A: 16 rows x 32B; B: 16 n-rows x 32B)
    const uint32_t aAddr = sb + (uint32_t)(wm*64 + (lane & 15)) * 80 + ((lane >> 4) << 4);
    const uint32_t bAddr = sb + 10240 +
        (uint32_t)(wn*32 + ((lane >> 3) & 1) * 8 + (lane & 7)) * 80 + ((lane >> 4) << 4);

    const int NKT = KP_ / 32;   // 96
    #pragma unroll 1
    for (int kt = 0; kt < NKT; kt++) {
        const int st = kt % 3;
        CP_WAIT1();
        __syncthreads();
        if (kt + 2 < NKT) LOADST(kt + 2, (kt + 2) % 3);
        const uint32_t so = (uint32_t)st * 20480u;
        #pragma unroll
        for (int ks = 0; ks < 2; ks++) {
            uint32_t afr[4][4], bfr[2][4];
            #pragma unroll
            for (int mt = 0; mt < 4; mt++)
                LDSM4(afr[mt], aAddr + so + (uint32_t)mt*16*80 + ks*32);
            #pragma unroll
            for (int nt2 = 0; nt2 < 2; nt2++)
                LDSM4(bfr[nt2], bAddr + so + (uint32_t)nt2*16*80 + ks*32);
            #pragma unroll
            for (int mt = 0; mt < 4; mt++)
                #pragma unroll
                for (int nt = 0; nt < 4; nt++)
                    MMA16816(acc[mt][nt], afr[mt],
                             bfr[nt >> 1][nt & 1], bfr[nt >> 1][2 + (nt & 1)]);
        }
    }
    CP_WAIT0();

    // epilogue: bias + store fp32
    const int crow = lane >> 2, ccol = (lane & 3) * 2;
    #pragma unroll
    for (int nt = 0; nt < 4; nt++) {
        const int n = (int)n0 + wn*32 + nt*8 + ccol;
        const float b0v = bias[n], b1v = bias[n + 1];
        #pragma unroll
        for (int mt = 0; mt < 4; mt++) {
            const size_t m = m0 + wm*64 + mt*16 + crow;
            float2 v0, v1;
            v0.x = acc[mt][nt][0] + b0v; v0.y = acc[mt][nt][1] + b1v;
            v1.x = acc[mt][nt][2] + b0v; v1.y = acc[mt][nt][3] + b1v;
            *(float2*)(C + m * 1024 + n)       = v0;
            *(float2*)(C + (m + 8) * 1024 + n) = v1;
        }
    }
    #undef LOADST
}

// ---------------- scores (fp32 SIMT, causal tiles, quirks fused) -----------
__global__ __launch_bounds__(256) void scores_kernel()
{
    const int kt = blockIdx.x, qt = blockIdx.y;
    if (kt > qt) return;
    const int bh = blockIdx.z;
    const int b = bh >> 4, h = bh & 15;

    __shared__ float Qs[64][65];
    __shared__ float Ks[64][65];
    const int t = threadIdx.x;

    const float* Qbase = g_Q + ((size_t)(b*S_ + qt*64)) * HE_ + h*64;
    const float* Kbase = g_K + ((size_t)(b*S_ + kt*64)) * HE_ + h*64;
    #pragma unroll
    for (int idx = t; idx < 4096; idx += 256) {
        const int r = idx >> 6, e = idx & 63;
        Qs[r][e] = Qbase[(size_t)r * HE_ + e];
        Ks[r][e] = Kbase[(size_t)r * HE_ + e];
    }
    __syncthreads();

    const int tx = t & 15, ty = t >> 4;
    const int r0 = ty * 4, c0 = tx * 4;
    float acc[4][4];
    #pragma unroll
    for (int i = 0; i < 4; i++)
        #pragma unroll
        for (int j = 0; j < 4; j++) acc[i][j] = 0.f;

    #pragma unroll 8
    for (int e = 0; e < 64; e++) {
        float a[4], bb[4];
        #pragma unroll
        for (int i = 0; i < 4; i++) a[i]  = Qs[r0 + i][e];
        #pragma unroll
        for (int j = 0; j < 4; j++) bb[j] = Ks[c0 + j][e];
        #pragma unroll
        for (int i = 0; i < 4; i++)
            #pragma unroll
            for (int j = 0; j < 4; j++) acc[i][j] = fmaf(a[i], bb[j], acc[i][j]);
    }

    const float scale = 0.35355339059327373f;  // 1/sqrt(8) batch-size quirk
    float* out = g_Sc + ((size_t)bh * S_ + qt*64) * S_ + kt*64;
    #pragma unroll
    for (int i = 0; i < 4; i++) {
        const int qg = qt*64 + r0 + i;
        #pragma unroll
        for (int j = 0; j < 4; j++) {
            const int kg = kt*64 + c0 + j;
            float v = acc[i][j] * scale;
            if (kg > qg || v == 0.0f) v = -1e9f;
            out[(size_t)(r0 + i) * S_ + (c0 + j)] = v;
        }
    }
}

// ---------------- softmax over heads (legacy dim=1 quirk) ------------------
__global__ void softmax_h_kernel()
{
    const int k = blockIdx.x * 256 + threadIdx.x;
    const int q = blockIdx.y;
    const int b = blockIdx.z;
    const int kmax = ((q >> 6) + 1) << 6;
    if (k >= kmax) return;

    const size_t base = (size_t)b * H_ * S_ * S_ + (size_t)q * S_ + k;
    const size_t hs   = (size_t)S_ * S_;
    float s[H_];
    float m = -3.4e38f;
    #pragma unroll
    for (int h = 0; h < H_; h++) { s[h] = g_Sc[base + h * hs]; m = fmaxf(m, s[h]); }
    float Z = 0.f;
    #pragma unroll
    for (int h = 0; h < H_; h++) { s[h] = expf(s[h] - m); Z += s[h]; }
    const float inv = 1.0f / Z;
    #pragma unroll
    for (int h = 0; h < H_; h++) g_Sc[base + h * hs] = s[h] * inv;
}

// ---------------- V tile sums + prefix scan --------------------------------
__global__ void tilesum_kernel()
{
    const int blk = blockIdx.x;
    const int e = threadIdx.x;
    const int tt = blk & (NT_ - 1);
    const int bh = blk / NT_;
    const int b = bh >> 4, h = bh & 15;
    const float* Vb = g_V + ((size_t)(b*S_ + tt*64)) * HE_ + h*64 + e;
    float sum = 0.f;
    #pragma unroll 8
    for (int k = 0; k < 64; k++) sum += Vb[(size_t)k * HE_];
    g_TS[((size_t)bh * NT_ + tt) * E_ + e] = sum;
}

__global__ void scan_kernel()
{
    const int id = blockIdx.x * 256 + threadIdx.x;
    const int e = id & 63, bh = id >> 6;
    float* P = g_P + (size_t)bh * (NT_ + 1) * E_;
    float p = 0.f;
    P[e] = 0.f;
    #pragma unroll
    for (int tt = 0; tt < NT_; tt++) {
        p += g_TS[((size_t)bh * NT_ + tt) * E_ + e];
        P[(tt + 1) * E_ + e] = p;
    }
}

// ---------------- attn @ V + analytic masked suffix ------------------------
__global__ __launch_bounds__(256) void attnv_kernel()
{
    const int qt = blockIdx.x, h = blockIdx.y, b = blockIdx.z;
    const int bh = b * H_ + h;

    __shared__ float As[64][65];
    __shared__ float Vs[64][65];
    const int t = threadIdx.x;
    const int tx = t & 15, ty = t >> 4;
    const int r0 = ty * 4, c0 = tx * 4;

    float acc[4][4];
    #pragma unroll
    for (int i = 0; i < 4; i++)
        #pragma unroll
        for (int j = 0; j < 4; j++) acc[i][j] = 0.f;

    const float* Sbase = g_Sc + ((size_t)bh * S_ + qt*64) * S_;
    for (int kt = 0; kt <= qt; kt++) {
        __syncthreads();
        #pragma unroll
        for (int idx = t; idx < 4096; idx += 256) {
            const int r = idx >> 6, c = idx & 63;
            As[r][c] = Sbase[(size_t)r * S_ + kt*64 + c];
            Vs[r][c] = g_V[((size_t)(b*S_ + kt*64 + r)) * HE_ + h*64 + c];
        }
        __syncthreads();
        #pragma unroll 8
        for (int k = 0; k < 64; k++) {
            float a[4], vv[4];
            #pragma unroll
            for (int i = 0; i < 4; i++) a[i]  = As[r0 + i][k];
            #pragma unroll
            for (int j = 0; j < 4; j++) vv[j] = Vs[k][c0 + j];
            #pragma unroll
            for (int i = 0; i < 4; i++)
                #pragma unroll
                for (int j = 0; j < 4; j++) acc[i][j] = fmaf(a[i], vv[j], acc[i][j]);
        }
    }

    const float* P = g_P + (size_t)bh * (NT_ + 1) * E_;
    float suf[4];
    #pragma unroll
    for (int j = 0; j < 4; j++)
        suf[j] = (P[NT_ * E_ + c0 + j] - P[(qt + 1) * E_ + c0 + j]) * 0.0625f;

    #pragma unroll
    for (int i = 0; i < 4; i++) {
        const size_t row = (size_t)(b*S_ + qt*64 + r0 + i);
        #pragma unroll
        for (int j = 0; j < 4; j++)
            g_AO[row * HE_ + h*64 + c0 + j] = acc[i][j] + suf[j];
    }
}

// ---------------- launch ---------------------------------------------------
extern "C" void kernel_launch(void* const* d_in, const int* in_sizes, int n_in,
                              void* d_out, int out_size)
{
    const float* X1 = (const float*)d_in[0];
    const float* X2 = (const float*)d_in[1];
    const float* Wq = (const float*)d_in[2];
    const float* bq = (const float*)d_in[3];
    const float* Wk = (const float*)d_in[4];
    const float* bk = (const float*)d_in[5];
    const float* Wv = (const float*)d_in[6];
    const float* bv = (const float*)d_in[7];
    const float* Wo = (const float*)d_in[8];
    const float* bo = (const float*)d_in[9];
    float* out = (float*)d_out;

    void *pQ, *pK, *pV, *pAO;
    void *pX1p, *pX2p, *pAOp, *pWqp, *pWkp, *pWvp, *pWop;
    cudaGetSymbolAddress(&pQ,  g_Q);   cudaGetSymbolAddress(&pK,  g_K);
    cudaGetSymbolAddress(&pV,  g_V);   cudaGetSymbolAddress(&pAO, g_AO);
    cudaGetSymbolAddress(&pX1p, g_X1p); cudaGetSymbolAddress(&pX2p, g_X2p);
    cudaGetSymbolAddress(&pAOp, g_AOp);
    cudaGetSymbolAddress(&pWqp, g_Wqp); cudaGetSymbolAddress(&pWkp, g_Wkp);
    cudaGetSymbolAddress(&pWvp, g_Wvp); cudaGetSymbolAddress(&pWop, g_Wop);

    const uint32_t SMEM_G = 61440;
    cudaFuncSetAttribute(gemm_mma_kernel,
                         cudaFuncAttributeMaxDynamicSharedMemorySize, SMEM_G);

    const int n4x = BS_ * D_ / 4;
    pack_x_kernel<<<n4x / 256, 256>>>(X1, (__nv_bfloat16*)pX1p, n4x);
    pack_x_kernel<<<n4x / 256, 256>>>(X2, (__nv_bfloat16*)pX2p, n4x);

    const dim3 gT(32, 32), bT(32, 8);
    pack_w_kernel<<<gT, bT>>>(Wq, (__nv_bfloat16*)pWqp);
    pack_w_kernel<<<gT, bT>>>(Wk, (__nv_bfloat16*)pWkp);
    pack_w_kernel<<<gT, bT>>>(Wv, (__nv_bfloat16*)pWvp);
    pack_w_kernel<<<gT, bT>>>(Wo, (__nv_bfloat16*)pWop);

    const dim3 gG(HE_ / 128, BS_ / 128);   // (8, 64)
    gemm_mma_kernel<<<gG, 256, SMEM_G>>>((__nv_bfloat16*)pX1p, (__nv_bfloat16*)pWqp, bq, (float*)pQ);
    gemm_mma_kernel<<<gG, 256, SMEM_G>>>((__nv_bfloat16*)pX2p, (__nv_bfloat16*)pWkp, bk, (float*)pK);
    gemm_mma_kernel<<<gG, 256, SMEM_G>>>((__nv_bfloat16*)pX2p, (__nv_bfloat16*)pWvp, bv, (float*)pV);

    tilesum_kernel<<<B_ * H_ * NT_, 64>>>();
    scan_kernel<<<(B_ * H_ * E_) / 256, 256>>>();

    scores_kernel<<<dim3(NT_, NT_, B_ * H_), 256>>>();
    softmax_h_kernel<<<dim3(S_ / 256, S_, B_), 256>>>();
    attnv_kernel<<<dim3(NT_, H_, B_), 256>>>();

    pack_x_kernel<<<n4x / 256, 256>>>((const float*)pAO, (__nv_bfloat16*)pAOp, n4x);
    gemm_mma_kernel<<<gG, 256, SMEM_G>>>((__nv_bfloat16*)pAOp, (__nv_bfloat16*)pWop, bo, out);
}

// round 4
// speedup vs baseline: 1.8111x; 1.3416x over previous
#include <cuda_runtime.h>
#include <cuda_bf16.h>
#include <cstdint>
#include <math.h>

#define B_  8
#define S_  1024
#define D_  1024
#define H_  16
#define E_  64
#define HE_ 1024
#define BS_ (B_*S_)
#define NT_ (S_/64)
#define KP_ 3072          // packed K for projections: [hi | lo | hi] x [hi | hi | lo]

// ---------------- scratch (device globals; no runtime allocation) ----------
__device__ float g_Q [B_*S_*HE_];
__device__ float g_K [B_*S_*HE_];
__device__ float g_V [B_*S_*HE_];
__device__ float g_AO[B_*S_*HE_];
__device__ float g_Sc[(size_t)B_*H_*S_*S_];
__device__ float g_TS[B_*H_*NT_*E_];
__device__ float g_P [B_*H_*(NT_+1)*E_];

// packed bf16 operands for projection GEMMs (K folded x3)
__device__ __nv_bfloat16 g_X1p[(size_t)BS_*KP_];
__device__ __nv_bfloat16 g_X2p[(size_t)BS_*KP_];
__device__ __nv_bfloat16 g_AOp[(size_t)BS_*KP_];
__device__ __nv_bfloat16 g_Wqp[(size_t)HE_*KP_];
__device__ __nv_bfloat16 g_Wkp[(size_t)HE_*KP_];
__device__ __nv_bfloat16 g_Wvp[(size_t)HE_*KP_];
__device__ __nv_bfloat16 g_Wop[(size_t)HE_*KP_];

// per-head bf16 hi/lo operands for attention mma
__device__ __nv_bfloat16 g_Qh[(size_t)B_*H_*S_*E_], g_Ql[(size_t)B_*H_*S_*E_];   // [bh][s][e]
__device__ __nv_bfloat16 g_Kh[(size_t)B_*H_*S_*E_], g_Kl[(size_t)B_*H_*S_*E_];   // [bh][s][e]
__device__ __nv_bfloat16 g_Vth[(size_t)B_*H_*E_*S_], g_Vtl[(size_t)B_*H_*E_*S_]; // [bh][e][s]
__device__ __nv_bfloat16 g_Ah[(size_t)B_*H_*S_*S_], g_Al[(size_t)B_*H_*S_*S_];   // [bh][q][k]

// ---------------- PTX helpers (baseline sm_80+) -----------------------------
__device__ __forceinline__ uint32_t smem_u32(const void* p) {
    uint32_t a;
    asm("{ .reg .u64 t; cvta.to.shared.u64 t, %1; cvt.u32.u64 %0, t; }" : "=r"(a) : "l"(p));
    return a;
}
__device__ __forceinline__ void cp16(uint32_t s, const void* g) {
    asm volatile("cp.async.cg.shared.global [%0], [%1], 16;" :: "r"(s), "l"(g));
}
#define CP_COMMIT() asm volatile("cp.async.commit_group;" ::: "memory")
#define CP_WAIT1()  asm volatile("cp.async.wait_group 1;" ::: "memory")
#define CP_WAIT0()  asm volatile("cp.async.wait_group 0;" ::: "memory")

#define LDSM4(r, a) \
    asm volatile("ldmatrix.sync.aligned.m8n8.x4.shared.b16 {%0,%1,%2,%3}, [%4];" \
        : "=r"((r)[0]), "=r"((r)[1]), "=r"((r)[2]), "=r"((r)[3]) : "r"(a))

#define MMA16816(c, a, b0v, b1v) \
    asm volatile("mma.sync.aligned.m16n8k16.row.col.f32.bf16.bf16.f32 " \
        "{%0,%1,%2,%3}, {%4,%5,%6,%7}, {%8,%9}, {%0,%1,%2,%3};" \
        : "+f"((c)[0]), "+f"((c)[1]), "+f"((c)[2]), "+f"((c)[3]) \
        : "r"((a)[0]), "r"((a)[1]), "r"((a)[2]), "r"((a)[3]), "r"(b0v), "r"(b1v))

// ---------------- pack kernels (projection GEMM operands) ------------------
__global__ __launch_bounds__(256) void pack_x_kernel(
    const float* __restrict__ in, __nv_bfloat16* __restrict__ out, int n4)
{
    int i = blockIdx.x * 256 + threadIdx.x;
    if (i >= n4) return;
    const int row = i >> 8;
    const int c   = (i & 255) * 4;
    float4 v = ((const float4*)in)[i];
    float f[4] = {v.x, v.y, v.z, v.w};
    __nv_bfloat162 h2[2], l2[2];
    #pragma unroll
    for (int j = 0; j < 2; j++) {
        __nv_bfloat16 h0 = __float2bfloat16_rn(f[2*j]);
        __nv_bfloat16 h1 = __float2bfloat16_rn(f[2*j+1]);
        __nv_bfloat16 l0 = __float2bfloat16_rn(f[2*j]   - __bfloat162float(h0));
        __nv_bfloat16 l1 = __float2bfloat16_rn(f[2*j+1] - __bfloat162float(h1));
        h2[j] = __nv_bfloat162(h0, h1);
        l2[j] = __nv_bfloat162(l0, l1);
    }
    __nv_bfloat16* base = out + (size_t)row * KP_;
    *(__nv_bfloat162*)(base + c)          = h2[0];
    *(__nv_bfloat162*)(base + c + 2)      = h2[1];
    *(__nv_bfloat162*)(base + 1024 + c)   = l2[0];
    *(__nv_bfloat162*)(base + 1024 + c+2) = l2[1];
    *(__nv_bfloat162*)(base + 2048 + c)   = h2[0];
    *(__nv_bfloat162*)(base + 2048 + c+2) = h2[1];
}

__global__ __launch_bounds__(256) void pack_w_kernel(
    const float* __restrict__ W, __nv_bfloat16* __restrict__ out)
{
    __shared__ float t[32][33];
    const int n0 = blockIdx.x * 32, k0 = blockIdx.y * 32;
    const int tx = threadIdx.x, ty = threadIdx.y;
    #pragma unroll
    for (int i = 0; i < 4; i++)
        t[ty + i*8][tx] = W[(size_t)(k0 + ty + i*8) * 1024 + n0 + tx];
    __syncthreads();
    #pragma unroll
    for (int i = 0; i < 4; i++) {
        float v = t[tx][ty + i*8];
        __nv_bfloat16 h = __float2bfloat16_rn(v);
        __nv_bfloat16 l = __float2bfloat16_rn(v - __bfloat162float(h));
        size_t o = (size_t)(n0 + ty + i*8) * KP_ + k0 + tx;
        out[o]        = h;
        out[o + 1024] = h;
        out[o + 2048] = l;
    }
}

// ---------------- projection GEMM (mma.sync bf16, K-fold x3) ---------------
__global__ __launch_bounds__(256) void gemm_mma_kernel(
    const __nv_bfloat16* __restrict__ Ap, const __nv_bfloat16* __restrict__ Bp,
    const float* __restrict__ bias, float* __restrict__ C)
{
    extern __shared__ char smch[];
    const uint32_t sb = smem_u32(smch);
    const int tid = threadIdx.x;
    const int lane = tid & 31, wid = tid >> 5;
    const int wm = wid >> 2, wn = wid & 3;
    const size_t m0 = (size_t)blockIdx.y * 128;
    const size_t n0 = (size_t)blockIdx.x * 128;

    const int lr = tid >> 2;
    const int lco = (tid & 3) * 16;
    const __nv_bfloat16* gA0 = Ap + (m0 + lr) * KP_ + (tid & 3) * 8;
    const __nv_bfloat16* gB0 = Bp + (n0 + lr) * KP_ + (tid & 3) * 8;
    const uint32_t smA = sb + lr * 80 + lco;
    const uint32_t smB = smA + 10240;

    float acc[4][4][4];
    #pragma unroll
    for (int a = 0; a < 4; a++)
        #pragma unroll
        for (int b = 0; b < 4; b++)
            #pragma unroll
            for (int c = 0; c < 4; c++) acc[a][b][c] = 0.f;

    #define LOADST(kt, st) do {                                        \
        const uint32_t so_ = (uint32_t)(st) * 20480u;                  \
        const __nv_bfloat16* ga_ = gA0 + (kt) * 32;                    \
        const __nv_bfloat16* gb_ = gB0 + (kt) * 32;                    \
        cp16(smA + so_,           ga_);                                \
        cp16(smA + so_ + 64*80,   ga_ + (size_t)64 * KP_);             \
        cp16(smB + so_,           gb_);                                \
        cp16(smB + so_ + 64*80,   gb_ + (size_t)64 * KP_);             \
        CP_COMMIT();                                                   \
    } while (0)

    LOADST(0, 0);
    LOADST(1, 1);

    const uint32_t aAddr = sb + (uint32_t)(wm*64 + (lane & 15)) * 80 + ((lane >> 4) << 4);
    const uint32_t bAddr = sb + 10240 +
        (uint32_t)(wn*32 + ((lane >> 3) & 1) * 8 + (lane & 7)) * 80 + ((lane >> 4) << 4);

    const int NKT = KP_ / 32;
    #pragma unroll 1
    for (int kt = 0; kt < NKT; kt++) {
        const int st = kt % 3;
        CP_WAIT1();
        __syncthreads();
        if (kt + 2 < NKT) LOADST(kt + 2, (kt + 2) % 3);
        const uint32_t so = (uint32_t)st * 20480u;
        #pragma unroll
        for (int ks = 0; ks < 2; ks++) {
            uint32_t afr[4][4], bfr[2][4];
            #pragma unroll
            for (int mt = 0; mt < 4; mt++)
                LDSM4(afr[mt], aAddr + so + (uint32_t)mt*16*80 + ks*32);
            #pragma unroll
            for (int nt2 = 0; nt2 < 2; nt2++)
                LDSM4(bfr[nt2], bAddr + so + (uint32_t)nt2*16*80 + ks*32);
            #pragma unroll
            for (int mt = 0; mt < 4; mt++)
                #pragma unroll
                for (int nt = 0; nt < 4; nt++)
                    MMA16816(acc[mt][nt], afr[mt],
                             bfr[nt >> 1][nt & 1], bfr[nt >> 1][2 + (nt & 1)]);
        }
    }
    CP_WAIT0();

    const int crow = lane >> 2, ccol = (lane & 3) * 2;
    #pragma unroll
    for (int nt = 0; nt < 4; nt++) {
        const int n = (int)n0 + wn*32 + nt*8 + ccol;
        const float b0v = bias[n], b1v = bias[n + 1];
        #pragma unroll
        for (int mt = 0; mt < 4; mt++) {
            const size_t m = m0 + wm*64 + mt*16 + crow;
            float2 v0, v1;
            v0.x = acc[mt][nt][0] + b0v; v0.y = acc[mt][nt][1] + b1v;
            v1.x = acc[mt][nt][2] + b0v; v1.y = acc[mt][nt][3] + b1v;
            *(float2*)(C + m * 1024 + n)       = v0;
            *(float2*)(C + (m + 8) * 1024 + n) = v1;
        }
    }
    #undef LOADST
}

// ---------------- convert Q/K to per-head bf16 hi/lo -----------------------
// in fp32 [b,s,(h,e)] -> out [bh][s][e]
__global__ __launch_bounds__(256) void cvt_qk_kernel(
    const float* __restrict__ in, __nv_bfloat16* __restrict__ oh,
    __nv_bfloat16* __restrict__ ol)
{
    const int i = blockIdx.x * 256 + threadIdx.x;   // float4 index
    const int gi = i * 4;
    const int e  = gi & 63;
    const int h  = (gi >> 6) & 15;
    const int s  = (gi >> 10) & 1023;
    const int b  = gi >> 20;
    float4 v = ((const float4*)in)[i];
    float f[4] = {v.x, v.y, v.z, v.w};
    __nv_bfloat16 hh[4], ll[4];
    #pragma unroll
    for (int j = 0; j < 4; j++) {
        hh[j] = __float2bfloat16_rn(f[j]);
        ll[j] = __float2bfloat16_rn(f[j] - __bfloat162float(hh[j]));
    }
    const size_t o = ((size_t)(b*16 + h) * 1024 + s) * 64 + e;
    *(__nv_bfloat162*)(oh + o)     = __nv_bfloat162(hh[0], hh[1]);
    *(__nv_bfloat162*)(oh + o + 2) = __nv_bfloat162(hh[2], hh[3]);
    *(__nv_bfloat162*)(ol + o)     = __nv_bfloat162(ll[0], ll[1]);
    *(__nv_bfloat162*)(ol + o + 2) = __nv_bfloat162(ll[2], ll[3]);
}

// ---------------- convert V to transposed per-head bf16 hi/lo --------------
// V fp32 [b,s,(h,e)] -> [bh][e][s]
__global__ void cvt_vt_kernel()
{
    __shared__ float t[32][33];
    const int bh = blockIdx.z;
    const int b = bh >> 4, h = bh & 15;
    const int s0 = blockIdx.y * 32, e0 = blockIdx.x * 32;
    const int tx = threadIdx.x, ty = threadIdx.y;
    #pragma unroll
    for (int i = 0; i < 4; i++)
        t[ty + i*8][tx] = g_V[((size_t)(b*1024) + s0 + ty + i*8) * 1024 + h*64 + e0 + tx];
    __syncthreads();
    #pragma unroll
    for (int i = 0; i < 4; i++) {
        float v = t[tx][ty + i*8];
        __nv_bfloat16 hh = __float2bfloat16_rn(v);
        __nv_bfloat16 ll = __float2bfloat16_rn(v - __bfloat162float(hh));
        const size_t o = ((size_t)bh * 64 + e0 + ty + i*8) * 1024 + s0 + tx;
        g_Vth[o] = hh;
        g_Vtl[o] = ll;
    }
}

// ---------------- scores via mma (bf16 x3), quirks fused -------------------
// grid (kt, qt, bh), block 128 (4 warps, 2x2 of 32x32)
__global__ __launch_bounds__(128) void scores_mma_kernel()
{
    const int kt = blockIdx.x, qt = blockIdx.y;
    if (kt > qt) return;
    const int bh = blockIdx.z;

    __shared__ __align__(16) char sm[4 * 64 * 144];
    const uint32_t sQH = smem_u32(sm);
    const uint32_t sQL = sQH +  9216;
    const uint32_t sKH = sQH + 18432;
    const uint32_t sKL = sQH + 27648;

    const int tid = threadIdx.x;
    const int lane = tid & 31, wid = tid >> 5;
    const int wm = wid >> 1, wn = wid & 1;

    const __nv_bfloat16* gQH = g_Qh + ((size_t)bh * 1024 + qt*64) * 64;
    const __nv_bfloat16* gQL = g_Ql + ((size_t)bh * 1024 + qt*64) * 64;
    const __nv_bfloat16* gKH = g_Kh + ((size_t)bh * 1024 + kt*64) * 64;
    const __nv_bfloat16* gKL = g_Kl + ((size_t)bh * 1024 + kt*64) * 64;
    #pragma unroll
    for (int i = tid; i < 512; i += 128) {
        const int r = i >> 3, c = i & 7;
        const size_t go = (size_t)r * 64 + c * 8;
        const uint32_t so = r * 144 + c * 16;
        *(uint4*)(sm + so)         = *(const uint4*)(gQH + go);
        *(uint4*)(sm + 9216 + so)  = *(const uint4*)(gQL + go);
        *(uint4*)(sm + 18432 + so) = *(const uint4*)(gKH + go);
        *(uint4*)(sm + 27648 + so) = *(const uint4*)(gKL + go);
    }
    __syncthreads();

    float acc[2][4][4];
    #pragma unroll
    for (int a = 0; a < 2; a++)
        #pragma unroll
        for (int b2 = 0; b2 < 4; b2++)
            #pragma unroll
            for (int c = 0; c < 4; c++) acc[a][b2][c] = 0.f;

    const uint32_t aOff = (uint32_t)(wm*32 + (lane & 15)) * 144 + ((lane >> 4) << 4);
    const uint32_t bOff = (uint32_t)(wn*32 + ((lane >> 3) & 1)*8 + (lane & 7)) * 144 + ((lane >> 4) << 4);

    #pragma unroll
    for (int es = 0; es < 4; es++) {
        const uint32_t cb = es * 32;
        uint32_t ah[2][4], al[2][4], bh2[2][4], bl[2][4];
        #pragma unroll
        for (int mt = 0; mt < 2; mt++) {
            LDSM4(ah[mt], sQH + aOff + (uint32_t)mt*16*144 + cb);
            LDSM4(al[mt], sQL + aOff + (uint32_t)mt*16*144 + cb);
        }
        #pragma unroll
        for (int nt2 = 0; nt2 < 2; nt2++) {
            LDSM4(bh2[nt2], sKH + bOff + (uint32_t)nt2*16*144 + cb);
            LDSM4(bl[nt2],  sKL + bOff + (uint32_t)nt2*16*144 + cb);
        }
        #pragma unroll
        for (int mt = 0; mt < 2; mt++)
            #pragma unroll
            for (int nt = 0; nt < 4; nt++) {
                MMA16816(acc[mt][nt], ah[mt], bh2[nt>>1][nt&1], bh2[nt>>1][2+(nt&1)]);
                MMA16816(acc[mt][nt], al[mt], bh2[nt>>1][nt&1], bh2[nt>>1][2+(nt&1)]);
                MMA16816(acc[mt][nt], ah[mt], bl[nt>>1][nt&1],  bl[nt>>1][2+(nt&1)]);
            }
    }

    const float scale = 0.35355339059327373f;  // 1/sqrt(8) batch-size quirk
    float* out = g_Sc + (size_t)bh * S_ * S_;
    #pragma unroll
    for (int mt = 0; mt < 2; mt++) {
        #pragma unroll
        for (int half = 0; half < 2; half++) {
            const int q = qt*64 + wm*32 + mt*16 + (lane >> 2) + half*8;
            #pragma unroll
            for (int nt = 0; nt < 4; nt++) {
                const int k0 = kt*64 + wn*32 + nt*8 + (lane & 3)*2;
                float v0 = acc[mt][nt][half*2]     * scale;
                float v1 = acc[mt][nt][half*2 + 1] * scale;
                if (k0     > q || v0 == 0.0f) v0 = -1e9f;
                if (k0 + 1 > q || v1 == 0.0f) v1 = -1e9f;
                *(float2*)(out + (size_t)q * S_ + k0) = make_float2(v0, v1);
            }
        }
    }
}

// ---------------- softmax over heads -> bf16 hi/lo attn --------------------
__global__ void softmax_h_kernel()
{
    const int k = blockIdx.x * 256 + threadIdx.x;
    const int q = blockIdx.y;
    const int b = blockIdx.z;
    const int kmax = ((q >> 6) + 1) << 6;
    if (k >= kmax) return;

    const size_t base = (size_t)b * H_ * S_ * S_ + (size_t)q * S_ + k;
    const size_t hs   = (size_t)S_ * S_;
    float s[H_];
    float m = -3.4e38f;
    #pragma unroll
    for (int h = 0; h < H_; h++) { s[h] = g_Sc[base + h * hs]; m = fmaxf(m, s[h]); }
    float Z = 0.f;
    #pragma unroll
    for (int h = 0; h < H_; h++) { s[h] = expf(s[h] - m); Z += s[h]; }
    const float inv = 1.0f / Z;
    #pragma unroll
    for (int h = 0; h < H_; h++) {
        const float a = s[h] * inv;
        const __nv_bfloat16 ah = __float2bfloat16_rn(a);
        const __nv_bfloat16 al = __float2bfloat16_rn(a - __bfloat162float(ah));
        g_Ah[base + h * hs] = ah;
        g_Al[base + h * hs] = al;
    }
}

// ---------------- V tile sums + prefix scan --------------------------------
__global__ void tilesum_kernel()
{
    const int blk = blockIdx.x;
    const int e = threadIdx.x;
    const int tt = blk & (NT_ - 1);
    const int bh = blk / NT_;
    const int b = bh >> 4, h = bh & 15;
    const float* Vb = g_V + ((size_t)(b*S_ + tt*64)) * HE_ + h*64 + e;
    float sum = 0.f;
    #pragma unroll 8
    for (int k = 0; k < 64; k++) sum += Vb[(size_t)k * HE_];
    g_TS[((size_t)bh * NT_ + tt) * E_ + e] = sum;
}

__global__ void scan_kernel()
{
    const int id = blockIdx.x * 256 + threadIdx.x;
    const int e = id & 63, bh = id >> 6;
    float* P = g_P + (size_t)bh * (NT_ + 1) * E_;
    float p = 0.f;
    P[e] = 0.f;
    #pragma unroll
    for (int tt = 0; tt < NT_; tt++) {
        p += g_TS[((size_t)bh * NT_ + tt) * E_ + e];
        P[(tt + 1) * E_ + e] = p;
    }
}

// ---------------- attn @ V via mma (bf16 x3) + masked suffix ---------------
// grid (qt, bh), block 128 (4 warps, 2x2 of 32x32)
__global__ __launch_bounds__(128) void attnv_mma_kernel()
{
    const int qt = blockIdx.x, bh = blockIdx.y;
    const int b = bh >> 4, h = bh & 15;

    __shared__ __align__(16) char sm[4 * 64 * 144];
    const uint32_t sAH = smem_u32(sm);
    const uint32_t sAL = sAH +  9216;
    const uint32_t sVH = sAH + 18432;
    const uint32_t sVL = sAH + 27648;

    const int tid = threadIdx.x;
    const int lane = tid & 31, wid = tid >> 5;
    const int wm = wid >> 1, wn = wid & 1;

    float acc[2][4][4];
    #pragma unroll
    for (int a = 0; a < 2; a++)
        #pragma unroll
        for (int b2 = 0; b2 < 4; b2++)
            #pragma unroll
            for (int c = 0; c < 4; c++) acc[a][b2][c] = 0.f;

    const uint32_t aOff = (uint32_t)(wm*32 + (lane & 15)) * 144 + ((lane >> 4) << 4);
    const uint32_t bOff = (uint32_t)(wn*32 + ((lane >> 3) & 1)*8 + (lane & 7)) * 144 + ((lane >> 4) << 4);

    const __nv_bfloat16* gAH0 = g_Ah + ((size_t)bh * 1024 + qt*64) * 1024;
    const __nv_bfloat16* gAL0 = g_Al + ((size_t)bh * 1024 + qt*64) * 1024;
    const __nv_bfloat16* gVH0 = g_Vth + (size_t)bh * 64 * 1024;
    const __nv_bfloat16* gVL0 = g_Vtl + (size_t)bh * 64 * 1024;

    for (int kt = 0; kt <= qt; kt++) {
        __syncthreads();
        #pragma unroll
        for (int i = tid; i < 512; i += 128) {
            const int r = i >> 3, c = i & 7;
            const size_t go = (size_t)r * 1024 + kt*64 + c * 8;
            const uint32_t so = r * 144 + c * 16;
            *(uint4*)(sm + so)         = *(const uint4*)(gAH0 + go);
            *(uint4*)(sm + 9216 + so)  = *(const uint4*)(gAL0 + go);
            *(uint4*)(sm + 18432 + so) = *(const uint4*)(gVH0 + go);
            *(uint4*)(sm + 27648 + so) = *(const uint4*)(gVL0 + go);
        }
        __syncthreads();

        #pragma unroll
        for (int ks = 0; ks < 4; ks++) {
            const uint32_t cb = ks * 32;
            uint32_t ah[2][4], al[2][4], vh[2][4], vl[2][4];
            #pragma unroll
            for (int mt = 0; mt < 2; mt++) {
                LDSM4(ah[mt], sAH + aOff + (uint32_t)mt*16*144 + cb);
                LDSM4(al[mt], sAL + aOff + (uint32_t)mt*16*144 + cb);
            }
            #pragma unroll
            for (int nt2 = 0; nt2 < 2; nt2++) {
                LDSM4(vh[nt2], sVH + bOff + (uint32_t)nt2*16*144 + cb);
                LDSM4(vl[nt2], sVL + bOff + (uint32_t)nt2*16*144 + cb);
            }
            #pragma unroll
            for (int mt = 0; mt < 2; mt++)
                #pragma unroll
                for (int nt = 0; nt < 4; nt++) {
                    MMA16816(acc[mt][nt], ah[mt], vh[nt>>1][nt&1], vh[nt>>1][2+(nt&1)]);
                    MMA16816(acc[mt][nt], al[mt], vh[nt>>1][nt&1], vh[nt>>1][2+(nt&1)]);
                    MMA16816(acc[mt][nt], ah[mt], vl[nt>>1][nt&1], vl[nt>>1][2+(nt&1)]);
                }
        }
    }

    // masked suffix: attn = 1/16 for all k beyond the causal tile band
    const float* P = g_P + (size_t)bh * (NT_ + 1) * E_;
    float* out = g_AO + ((size_t)(b*S_ + qt*64)) * HE_ + h*64;
    #pragma unroll
    for (int nt = 0; nt < 4; nt++) {
        const int e0 = wn*32 + nt*8 + (lane & 3)*2;
        const float s0 = (P[NT_*E_ + e0]     - P[(qt+1)*E_ + e0])     * 0.0625f;
        const float s1 = (P[NT_*E_ + e0 + 1] - P[(qt+1)*E_ + e0 + 1]) * 0.0625f;
        #pragma unroll
        for (int mt = 0; mt < 2; mt++) {
            #pragma unroll
            for (int half = 0; half < 2; half++) {
                const int q = wm*32 + mt*16 + (lane >> 2) + half*8;
                float2 v;
                v.x = acc[mt][nt][half*2]     + s0;
                v.y = acc[mt][nt][half*2 + 1] + s1;
                *(float2*)(out + (size_t)q * HE_ + e0) = v;
            }
        }
    }
}

// ---------------- launch ---------------------------------------------------
extern "C" void kernel_launch(void* const* d_in, const int* in_sizes, int n_in,
                              void* d_out, int out_size)
{
    const float* X1 = (const float*)d_in[0];
    const float* X2 = (const float*)d_in[1];
    const float* Wq = (const float*)d_in[2];
    const float* bq = (const float*)d_in[3];
    const float* Wk = (const float*)d_in[4];
    const float* bk = (const float*)d_in[5];
    const float* Wv = (const float*)d_in[6];
    const float* bv = (const float*)d_in[7];
    const float* Wo = (const float*)d_in[8];
    const float* bo = (const float*)d_in[9];
    float* out = (float*)d_out;

    void *pQ, *pK, *pV, *pAO;
    void *pX1p, *pX2p, *pAOp, *pWqp, *pWkp, *pWvp, *pWop;
    void *pQh, *pQl, *pKh, *pKl;
    cudaGetSymbolAddress(&pQ,  g_Q);   cudaGetSymbolAddress(&pK,  g_K);
    cudaGetSymbolAddress(&pV,  g_V);   cudaGetSymbolAddress(&pAO, g_AO);
    cudaGetSymbolAddress(&pX1p, g_X1p); cudaGetSymbolAddress(&pX2p, g_X2p);
    cudaGetSymbolAddress(&pAOp, g_AOp);
    cudaGetSymbolAddress(&pWqp, g_Wqp); cudaGetSymbolAddress(&pWkp, g_Wkp);
    cudaGetSymbolAddress(&pWvp, g_Wvp); cudaGetSymbolAddress(&pWop, g_Wop);
    cudaGetSymbolAddress(&pQh, g_Qh);   cudaGetSymbolAddress(&pQl, g_Ql);
    cudaGetSymbolAddress(&pKh, g_Kh);   cudaGetSymbolAddress(&pKl, g_Kl);

    const uint32_t SMEM_G = 61440;
    cudaFuncSetAttribute(gemm_mma_kernel,
                         cudaFuncAttributeMaxDynamicSharedMemorySize, SMEM_G);

    const int n4x = BS_ * D_ / 4;
    pack_x_kernel<<<n4x / 256, 256>>>(X1, (__nv_bfloat16*)pX1p, n4x);
    pack_x_kernel<<<n4x / 256, 256>>>(X2, (__nv_bfloat16*)pX2p, n4x);

    const dim3 gT(32, 32), bT(32, 8);
    pack_w_kernel<<<gT, bT>>>(Wq, (__nv_bfloat16*)pWqp);
    pack_w_kernel<<<gT, bT>>>(Wk, (__nv_bfloat16*)pWkp);
    pack_w_kernel<<<gT, bT>>>(Wv, (__nv_bfloat16*)pWvp);
    pack_w_kernel<<<gT, bT>>>(Wo, (__nv_bfloat16*)pWop);

    const dim3 gG(HE_ / 128, BS_ / 128);
    gemm_mma_kernel<<<gG, 256, SMEM_G>>>((__nv_bfloat16*)pX1p, (__nv_bfloat16*)pWqp, bq, (float*)pQ);
    gemm_mma_kernel<<<gG, 256, SMEM_G>>>((__nv_bfloat16*)pX2p, (__nv_bfloat16*)pWkp, bk, (float*)pK);
    gemm_mma_kernel<<<gG, 256, SMEM_G>>>((__nv_bfloat16*)pX2p, (__nv_bfloat16*)pWvp, bv, (float*)pV);

    // hi/lo conversions for attention mma
    cvt_qk_kernel<<<(BS_*HE_/4) / 256, 256>>>((const float*)pQ, (__nv_bfloat16*)pQh, (__nv_bfloat16*)pQl);
    cvt_qk_kernel<<<(BS_*HE_/4) / 256, 256>>>((const float*)pK, (__nv_bfloat16*)pKh, (__nv_bfloat16*)pKl);
    cvt_vt_kernel<<<dim3(2, 32, B_*H_), dim3(32, 8)>>>();

    tilesum_kernel<<<B_ * H_ * NT_, 64>>>();
    scan_kernel<<<(B_ * H_ * E_) / 256, 256>>>();

    scores_mma_kernel<<<dim3(NT_, NT_, B_ * H_), 128>>>();
    softmax_h_kernel<<<dim3(S_ / 256, S_, B_), 256>>>();
    attnv_mma_kernel<<<dim3(NT_, B_ * H_), 128>>>();

    pack_x_kernel<<<n4x / 256, 256>>>((const float*)pAO, (__nv_bfloat16*)pAOp, n4x);
    gemm_mma_kernel<<<gG, 256, SMEM_G>>>((__nv_bfloat16*)pAOp, (__nv_bfloat16*)pWop, bo, out);
}

// round 5
// speedup vs baseline: 2.6065x; 1.4392x over previous
#include <cuda_runtime.h>
#include <cuda_fp16.h>
#include <cstdint>
#include <math.h>

#define B_  8
#define S_  1024
#define D_  1024
#define H_  16
#define E_  64
#define HE_ 1024
#define BS_ (B_*S_)
#define NT_ (S_/64)
#define KP_ 2048          // packed K for projections: [Xh | Xl] x [Wh | Wh]

// ---------------- scratch (device globals; no runtime allocation) ----------
__device__ float g_V [B_*S_*HE_];
__device__ float g_Sc[(size_t)B_*H_*S_*S_];
__device__ float g_TS[B_*H_*NT_*E_];
__device__ float g_P [B_*H_*(NT_+1)*E_];

// packed fp16 operands for projection GEMMs (K folded x2)
__device__ __half g_X1p[(size_t)BS_*KP_];
__device__ __half g_X2p[(size_t)BS_*KP_];
__device__ __half g_AOp[(size_t)BS_*KP_];
__device__ __half g_Wqp[(size_t)HE_*KP_];
__device__ __half g_Wkp[(size_t)HE_*KP_];
__device__ __half g_Wvp[(size_t)HE_*KP_];
__device__ __half g_Wop[(size_t)HE_*KP_];

// per-head fp16 operands for attention mma
__device__ __half g_Qh[(size_t)B_*H_*S_*E_], g_Ql[(size_t)B_*H_*S_*E_];  // [bh][s][e]
__device__ __half g_Kh[(size_t)B_*H_*S_*E_];                             // [bh][s][e]
__device__ __half g_Vth[(size_t)B_*H_*E_*S_];                            // [bh][e][s]
__device__ __half g_Ah[(size_t)B_*H_*S_*S_], g_Al[(size_t)B_*H_*S_*S_];  // [bh][q][k]

// ---------------- PTX helpers (baseline sm_80+) -----------------------------
__device__ __forceinline__ uint32_t smem_u32(const void* p) {
    uint32_t a;
    asm("{ .reg .u64 t; cvta.to.shared.u64 t, %1; cvt.u32.u64 %0, t; }" : "=r"(a) : "l"(p));
    return a;
}
__device__ __forceinline__ void cp16(uint32_t s, const void* g) {
    asm volatile("cp.async.cg.shared.global [%0], [%1], 16;" :: "r"(s), "l"(g));
}
#define CP_COMMIT() asm volatile("cp.async.commit_group;" ::: "memory")
#define CP_WAIT1()  asm volatile("cp.async.wait_group 1;" ::: "memory")
#define CP_WAIT0()  asm volatile("cp.async.wait_group 0;" ::: "memory")

#define LDSM4(r, a) \
    asm volatile("ldmatrix.sync.aligned.m8n8.x4.shared.b16 {%0,%1,%2,%3}, [%4];" \
        : "=r"((r)[0]), "=r"((r)[1]), "=r"((r)[2]), "=r"((r)[3]) : "r"(a))

#define MMAF16(c, a, b0v, b1v) \
    asm volatile("mma.sync.aligned.m16n8k16.row.col.f32.f16.f16.f32 " \
        "{%0,%1,%2,%3}, {%4,%5,%6,%7}, {%8,%9}, {%0,%1,%2,%3};" \
        : "+f"((c)[0]), "+f"((c)[1]), "+f"((c)[2]), "+f"((c)[3]) \
        : "r"((a)[0]), "r"((a)[1]), "r"((a)[2]), "r"((a)[3]), "r"(b0v), "r"(b1v))

// ---------------- pack kernels ---------------------------------------------
// X fp32 [R,1024] -> fp16 [R,2048] as [hi | lo]
__global__ __launch_bounds__(256) void pack_x_kernel(
    const float* __restrict__ in, __half* __restrict__ out, int n4)
{
    int i = blockIdx.x * 256 + threadIdx.x;
    if (i >= n4) return;
    const int row = i >> 8;
    const int c   = (i & 255) * 4;
    float4 v = ((const float4*)in)[i];
    float f[4] = {v.x, v.y, v.z, v.w};
    __half hh[4], ll[4];
    #pragma unroll
    for (int j = 0; j < 4; j++) {
        hh[j] = __float2half_rn(f[j]);
        ll[j] = __float2half_rn(f[j] - __half2float(hh[j]));
    }
    __half* base = out + (size_t)row * KP_;
    *(__half2*)(base + c)          = __half2(hh[0], hh[1]);
    *(__half2*)(base + c + 2)      = __half2(hh[2], hh[3]);
    *(__half2*)(base + 1024 + c)   = __half2(ll[0], ll[1]);
    *(__half2*)(base + 1024 + c+2) = __half2(ll[2], ll[3]);
}

// W fp32 [K=1024, N=1024] -> Wt fp16 [N, 2048] as [hi | hi]
__global__ __launch_bounds__(256) void pack_w_kernel(
    const float* __restrict__ W, __half* __restrict__ out)
{
    __shared__ float t[32][33];
    const int n0 = blockIdx.x * 32, k0 = blockIdx.y * 32;
    const int tx = threadIdx.x, ty = threadIdx.y;
    #pragma unroll
    for (int i = 0; i < 4; i++)
        t[ty + i*8][tx] = W[(size_t)(k0 + ty + i*8) * 1024 + n0 + tx];
    __syncthreads();
    #pragma unroll
    for (int i = 0; i < 4; i++) {
        float v = t[tx][ty + i*8];
        __half h = __float2half_rn(v);
        size_t o = (size_t)(n0 + ty + i*8) * KP_ + k0 + tx;
        out[o]        = h;
        out[o + 1024] = h;
    }
}

// ---------------- projection GEMM (mma.sync fp16, K-fold x2) ---------------
// epilogue modes: 0 = fp32 C row-major; 1 = per-head fp16 hi+lo; 2 = per-head fp16 hi
__global__ __launch_bounds__(256) void gemm_mma_kernel(
    const __half* __restrict__ Ap, const __half* __restrict__ Bp,
    const float* __restrict__ bias, float* __restrict__ C,
    __half* __restrict__ Oh, __half* __restrict__ Ol, int mode)
{
    extern __shared__ char smch[];
    const uint32_t sb = smem_u32(smch);
    const int tid = threadIdx.x;
    const int lane = tid & 31, wid = tid >> 5;
    const int wm = wid >> 2, wn = wid & 3;
    const size_t m0 = (size_t)blockIdx.y * 128;
    const size_t n0 = (size_t)blockIdx.x * 128;

    const int lr = tid >> 2;
    const int lco = (tid & 3) * 16;
    const __half* gA0 = Ap + (m0 + lr) * KP_ + (tid & 3) * 8;
    const __half* gB0 = Bp + (n0 + lr) * KP_ + (tid & 3) * 8;
    const uint32_t smA = sb + lr * 80 + lco;
    const uint32_t smB = smA + 10240;

    float acc[4][4][4];
    #pragma unroll
    for (int a = 0; a < 4; a++)
        #pragma unroll
        for (int b = 0; b < 4; b++)
            #pragma unroll
            for (int c = 0; c < 4; c++) acc[a][b][c] = 0.f;

    #define LOADST(kt, st) do {                                        \
        const uint32_t so_ = (uint32_t)(st) * 20480u;                  \
        const __half* ga_ = gA0 + (kt) * 32;                           \
        const __half* gb_ = gB0 + (kt) * 32;                           \
        cp16(smA + so_,           ga_);                                \
        cp16(smA + so_ + 64*80,   ga_ + (size_t)64 * KP_);             \
        cp16(smB + so_,           gb_);                                \
        cp16(smB + so_ + 64*80,   gb_ + (size_t)64 * KP_);             \
        CP_COMMIT();                                                   \
    } while (0)

    LOADST(0, 0);
    LOADST(1, 1);

    const uint32_t aAddr = sb + (uint32_t)(wm*64 + (lane & 15)) * 80 + ((lane >> 4) << 4);
    const uint32_t bAddr = sb + 10240 +
        (uint32_t)(wn*32 + ((lane >> 3) & 1) * 8 + (lane & 7)) * 80 + ((lane >> 4) << 4);

    const int NKT = KP_ / 32;   // 64
    #pragma unroll 1
    for (int kt = 0; kt < NKT; kt++) {
        const int st = kt % 3;
        CP_WAIT1();
        __syncthreads();
        if (kt + 2 < NKT) LOADST(kt + 2, (kt + 2) % 3);
        const uint32_t so = (uint32_t)st * 20480u;
        #pragma unroll
        for (int ks = 0; ks < 2; ks++) {
            uint32_t afr[4][4], bfr[2][4];
            #pragma unroll
            for (int mt = 0; mt < 4; mt++)
                LDSM4(afr[mt], aAddr + so + (uint32_t)mt*16*80 + ks*32);
            #pragma unroll
            for (int nt2 = 0; nt2 < 2; nt2++)
                LDSM4(bfr[nt2], bAddr + so + (uint32_t)nt2*16*80 + ks*32);
            #pragma unroll
            for (int mt = 0; mt < 4; mt++)
                #pragma unroll
                for (int nt = 0; nt < 4; nt++)
                    MMAF16(acc[mt][nt], afr[mt],
                           bfr[nt >> 1][nt & 1], bfr[nt >> 1][2 + (nt & 1)]);
        }
    }
    CP_WAIT0();

    const int crow = lane >> 2, ccol = (lane & 3) * 2;
    if (mode == 0) {
        #pragma unroll
        for (int nt = 0; nt < 4; nt++) {
            const int n = (int)n0 + wn*32 + nt*8 + ccol;
            const float b0v = bias[n], b1v = bias[n + 1];
            #pragma unroll
            for (int mt = 0; mt < 4; mt++) {
                const size_t m = m0 + wm*64 + mt*16 + crow;
                float2 v0, v1;
                v0.x = acc[mt][nt][0] + b0v; v0.y = acc[mt][nt][1] + b1v;
                v1.x = acc[mt][nt][2] + b0v; v1.y = acc[mt][nt][3] + b1v;
                *(float2*)(C + m * 1024 + n)       = v0;
                *(float2*)(C + (m + 8) * 1024 + n) = v1;
            }
        }
    } else {
        #pragma unroll
        for (int nt = 0; nt < 4; nt++) {
            const int n = (int)n0 + wn*32 + nt*8 + ccol;
            const float b0v = bias[n], b1v = bias[n + 1];
            const int h = n >> 6, e = n & 63;
            #pragma unroll
            for (int mt = 0; mt < 4; mt++) {
                #pragma unroll
                for (int half = 0; half < 2; half++) {
                    const size_t m = m0 + wm*64 + mt*16 + crow + half*8;
                    const int b2 = (int)(m >> 10), s = (int)(m & 1023);
                    const size_t o = (((size_t)(b2*16 + h) * 1024 + s) * 64 + e);
                    const float v0 = acc[mt][nt][half*2]     + b0v;
                    const float v1 = acc[mt][nt][half*2 + 1] + b1v;
                    const __half h0 = __float2half_rn(v0);
                    const __half h1 = __float2half_rn(v1);
                    *(__half2*)(Oh + o) = __half2(h0, h1);
                    if (mode == 1) {
                        const __half l0 = __float2half_rn(v0 - __half2float(h0));
                        const __half l1 = __float2half_rn(v1 - __half2float(h1));
                        *(__half2*)(Ol + o) = __half2(l0, l1);
                    }
                }
            }
        }
    }
    #undef LOADST
}

// ---------------- V fp32 -> transposed per-head fp16 hi --------------------
__global__ void cvt_vt_kernel()
{
    __shared__ float t[32][33];
    const int bh = blockIdx.z;
    const int b = bh >> 4, h = bh & 15;
    const int s0 = blockIdx.y * 32, e0 = blockIdx.x * 32;
    const int tx = threadIdx.x, ty = threadIdx.y;
    #pragma unroll
    for (int i = 0; i < 4; i++)
        t[ty + i*8][tx] = g_V[((size_t)(b*1024) + s0 + ty + i*8) * 1024 + h*64 + e0 + tx];
    __syncthreads();
    #pragma unroll
    for (int i = 0; i < 4; i++) {
        const float v = t[tx][ty + i*8];
        g_Vth[((size_t)bh * 64 + e0 + ty + i*8) * 1024 + s0 + tx] = __float2half_rn(v);
    }
}

// ---------------- scores via mma (fp16 x2), quirks fused -------------------
// grid (kt, qt, bh), block 128 (4 warps, 2x2 of 32x32)
__global__ __launch_bounds__(128) void scores_mma_kernel()
{
    const int kt = blockIdx.x, qt = blockIdx.y;
    if (kt > qt) return;
    const int bh = blockIdx.z;

    __shared__ __align__(16) char sm[3 * 64 * 144];
    const uint32_t sQH = smem_u32(sm);
    const uint32_t sQL = sQH +  9216;
    const uint32_t sKH = sQH + 18432;

    const int tid = threadIdx.x;
    const int lane = tid & 31, wid = tid >> 5;
    const int wm = wid >> 1, wn = wid & 1;

    const __half* gQH = g_Qh + ((size_t)bh * 1024 + qt*64) * 64;
    const __half* gQL = g_Ql + ((size_t)bh * 1024 + qt*64) * 64;
    const __half* gKH = g_Kh + ((size_t)bh * 1024 + kt*64) * 64;
    #pragma unroll
    for (int i = tid; i < 512; i += 128) {
        const int r = i >> 3, c = i & 7;
        const size_t go = (size_t)r * 64 + c * 8;
        const uint32_t so = r * 144 + c * 16;
        *(uint4*)(sm + so)         = *(const uint4*)(gQH + go);
        *(uint4*)(sm + 9216 + so)  = *(const uint4*)(gQL + go);
        *(uint4*)(sm + 18432 + so) = *(const uint4*)(gKH + go);
    }
    __syncthreads();

    float acc[2][4][4];
    #pragma unroll
    for (int a = 0; a < 2; a++)
        #pragma unroll
        for (int b2 = 0; b2 < 4; b2++)
            #pragma unroll
            for (int c = 0; c < 4; c++) acc[a][b2][c] = 0.f;

    const uint32_t aOff = (uint32_t)(wm*32 + (lane & 15)) * 144 + ((lane >> 4) << 4);
    const uint32_t bOff = (uint32_t)(wn*32 + ((lane >> 3) & 1)*8 + (lane & 7)) * 144 + ((lane >> 4) << 4);

    #pragma unroll
    for (int es = 0; es < 4; es++) {
        const uint32_t cb = es * 32;
        uint32_t ah[2][4], al[2][4], bh2[2][4];
        #pragma unroll
        for (int mt = 0; mt < 2; mt++) {
            LDSM4(ah[mt], sQH + aOff + (uint32_t)mt*16*144 + cb);
            LDSM4(al[mt], sQL + aOff + (uint32_t)mt*16*144 + cb);
        }
        #pragma unroll
        for (int nt2 = 0; nt2 < 2; nt2++)
            LDSM4(bh2[nt2], sKH + bOff + (uint32_t)nt2*16*144 + cb);
        #pragma unroll
        for (int mt = 0; mt < 2; mt++)
            #pragma unroll
            for (int nt = 0; nt < 4; nt++) {
                MMAF16(acc[mt][nt], ah[mt], bh2[nt>>1][nt&1], bh2[nt>>1][2+(nt&1)]);
                MMAF16(acc[mt][nt], al[mt], bh2[nt>>1][nt&1], bh2[nt>>1][2+(nt&1)]);
            }
    }

    const float scale = 0.35355339059327373f;  // 1/sqrt(8) batch-size quirk
    float* out = g_Sc + (size_t)bh * S_ * S_;
    #pragma unroll
    for (int mt = 0; mt < 2; mt++) {
        #pragma unroll
        for (int half = 0; half < 2; half++) {
            const int q = qt*64 + wm*32 + mt*16 + (lane >> 2) + half*8;
            #pragma unroll
            for (int nt = 0; nt < 4; nt++) {
                const int k0 = kt*64 + wn*32 + nt*8 + (lane & 3)*2;
                float v0 = acc[mt][nt][half*2]     * scale;
                float v1 = acc[mt][nt][half*2 + 1] * scale;
                if (k0     > q || v0 == 0.0f) v0 = -1e9f;
                if (k0 + 1 > q || v1 == 0.0f) v1 = -1e9f;
                *(float2*)(out + (size_t)q * S_ + k0) = make_float2(v0, v1);
            }
        }
    }
}

// ---------------- softmax over heads -> fp16 hi/lo attn --------------------
__global__ void softmax_h_kernel()
{
    const int k = blockIdx.x * 256 + threadIdx.x;
    const int q = blockIdx.y;
    const int b = blockIdx.z;
    const int kmax = ((q >> 6) + 1) << 6;
    if (k >= kmax) return;

    const size_t base = (size_t)b * H_ * S_ * S_ + (size_t)q * S_ + k;
    const size_t hs   = (size_t)S_ * S_;
    float s[H_];
    float m = -3.4e38f;
    #pragma unroll
    for (int h = 0; h < H_; h++) { s[h] = g_Sc[base + h * hs]; m = fmaxf(m, s[h]); }
    float Z = 0.f;
    #pragma unroll
    for (int h = 0; h < H_; h++) { s[h] = expf(s[h] - m); Z += s[h]; }
    const float inv = 1.0f / Z;
    #pragma unroll
    for (int h = 0; h < H_; h++) {
        const float a = s[h] * inv;
        const __half ah = __float2half_rn(a);
        g_Ah[base + h * hs] = ah;
        g_Al[base + h * hs] = __float2half_rn(a - __half2float(ah));
    }
}

// ---------------- V tile sums + prefix scan --------------------------------
__global__ void tilesum_kernel()
{
    const int blk = blockIdx.x;
    const int e = threadIdx.x;
    const int tt = blk & (NT_ - 1);
    const int bh = blk / NT_;
    const int b = bh >> 4, h = bh & 15;
    const float* Vb = g_V + ((size_t)(b*S_ + tt*64)) * HE_ + h*64 + e;
    float sum = 0.f;
    #pragma unroll 8
    for (int k = 0; k < 64; k++) sum += Vb[(size_t)k * HE_];
    g_TS[((size_t)bh * NT_ + tt) * E_ + e] = sum;
}

__global__ void scan_kernel()
{
    const int id = blockIdx.x * 256 + threadIdx.x;
    const int e = id & 63, bh = id >> 6;
    float* P = g_P + (size_t)bh * (NT_ + 1) * E_;
    float p = 0.f;
    P[e] = 0.f;
    #pragma unroll
    for (int tt = 0; tt < NT_; tt++) {
        p += g_TS[((size_t)bh * NT_ + tt) * E_ + e];
        P[(tt + 1) * E_ + e] = p;
    }
}

// ---------------- attn @ V via mma (fp16 x2) + masked suffix ---------------
// grid (qt, bh), block 128; epilogue writes PACKED fold-2048 AO operand
__global__ __launch_bounds__(128) void attnv_mma_kernel()
{
    const int qt = blockIdx.x, bh = blockIdx.y;
    const int b = bh >> 4, h = bh & 15;

    __shared__ __align__(16) char sm[3 * 64 * 144];
    const uint32_t sAH = smem_u32(sm);
    const uint32_t sAL = sAH +  9216;
    const uint32_t sVH = sAH + 18432;

    const int tid = threadIdx.x;
    const int lane = tid & 31, wid = tid >> 5;
    const int wm = wid >> 1, wn = wid & 1;

    float acc[2][4][4];
    #pragma unroll
    for (int a = 0; a < 2; a++)
        #pragma unroll
        for (int b2 = 0; b2 < 4; b2++)
            #pragma unroll
            for (int c = 0; c < 4; c++) acc[a][b2][c] = 0.f;

    const uint32_t aOff = (uint32_t)(wm*32 + (lane & 15)) * 144 + ((lane >> 4) << 4);
    const uint32_t bOff = (uint32_t)(wn*32 + ((lane >> 3) & 1)*8 + (lane & 7)) * 144 + ((lane >> 4) << 4);

    const __half* gAH0 = g_Ah + ((size_t)bh * 1024 + qt*64) * 1024;
    const __half* gAL0 = g_Al + ((size_t)bh * 1024 + qt*64) * 1024;
    const __half* gVH0 = g_Vth + (size_t)bh * 64 * 1024;

    for (int kt = 0; kt <= qt; kt++) {
        __syncthreads();
        #pragma unroll
        for (int i = tid; i < 512; i += 128) {
            const int r = i >> 3, c = i & 7;
            const size_t go = (size_t)r * 1024 + kt*64 + c * 8;
            const uint32_t so = r * 144 + c * 16;
            *(uint4*)(sm + so)         = *(const uint4*)(gAH0 + go);
            *(uint4*)(sm + 9216 + so)  = *(const uint4*)(gAL0 + go);
            *(uint4*)(sm + 18432 + so) = *(const uint4*)(gVH0 + go);
        }
        __syncthreads();

        #pragma unroll
        for (int ks = 0; ks < 4; ks++) {
            const uint32_t cb = ks * 32;
            uint32_t ah[2][4], al[2][4], vh[2][4];
            #pragma unroll
            for (int mt = 0; mt < 2; mt++) {
                LDSM4(ah[mt], sAH + aOff + (uint32_t)mt*16*144 + cb);
                LDSM4(al[mt], sAL + aOff + (uint32_t)mt*16*144 + cb);
            }
            #pragma unroll
            for (int nt2 = 0; nt2 < 2; nt2++)
                LDSM4(vh[nt2], sVH + bOff + (uint32_t)nt2*16*144 + cb);
            #pragma unroll
            for (int mt = 0; mt < 2; mt++)
                #pragma unroll
                for (int nt = 0; nt < 4; nt++) {
                    MMAF16(acc[mt][nt], ah[mt], vh[nt>>1][nt&1], vh[nt>>1][2+(nt&1)]);
                    MMAF16(acc[mt][nt], al[mt], vh[nt>>1][nt&1], vh[nt>>1][2+(nt&1)]);
                }
        }
    }

    // masked suffix: attn = 1/16 exactly for k beyond causal band; then write
    // packed [hi | lo] fold-2048 operand for the output projection GEMM.
    const float* P = g_P + (size_t)bh * (NT_ + 1) * E_;
    #pragma unroll
    for (int nt = 0; nt < 4; nt++) {
        const int e0 = wn*32 + nt*8 + (lane & 3)*2;
        const float s0 = (P[NT_*E_ + e0]     - P[(qt+1)*E_ + e0])     * 0.0625f;
        const float s1 = (P[NT_*E_ + e0 + 1] - P[(qt+1)*E_ + e0 + 1]) * 0.0625f;
        #pragma unroll
        for (int mt = 0; mt < 2; mt++) {
            #pragma unroll
            for (int half = 0; half < 2; half++) {
                const int q = wm*32 + mt*16 + (lane >> 2) + half*8;
                const float v0 = acc[mt][nt][half*2]     + s0;
                const float v1 = acc[mt][nt][half*2 + 1] + s1;
                const __half h0 = __float2half_rn(v0);
                const __half h1 = __float2half_rn(v1);
                const __half l0 = __float2half_rn(v0 - __half2float(h0));
                const __half l1 = __float2half_rn(v1 - __half2float(h1));
                __half* base = g_AOp + ((size_t)(b*1024 + qt*64 + q)) * KP_ + h*64 + e0;
                *(__half2*)(base)        = __half2(h0, h1);
                *(__half2*)(base + 1024) = __half2(l0, l1);
            }
        }
    }
}

// ---------------- launch ---------------------------------------------------
extern "C" void kernel_launch(void* const* d_in, const int* in_sizes, int n_in,
                              void* d_out, int out_size)
{
    const float* X1 = (const float*)d_in[0];
    const float* X2 = (const float*)d_in[1];
    const float* Wq = (const float*)d_in[2];
    const float* bq = (const float*)d_in[3];
    const float* Wk = (const float*)d_in[4];
    const float* bk = (const float*)d_in[5];
    const float* Wv = (const float*)d_in[6];
    const float* bv = (const float*)d_in[7];
    const float* Wo = (const float*)d_in[8];
    const float* bo = (const float*)d_in[9];
    float* out = (float*)d_out;

    void *pV;
    void *pX1p, *pX2p, *pAOp, *pWqp, *pWkp, *pWvp, *pWop;
    void *pQh, *pQl, *pKh;
    cudaGetSymbolAddress(&pV,  g_V);
    cudaGetSymbolAddress(&pX1p, g_X1p); cudaGetSymbolAddress(&pX2p, g_X2p);
    cudaGetSymbolAddress(&pAOp, g_AOp);
    cudaGetSymbolAddress(&pWqp, g_Wqp); cudaGetSymbolAddress(&pWkp, g_Wkp);
    cudaGetSymbolAddress(&pWvp, g_Wvp); cudaGetSymbolAddress(&pWop, g_Wop);
    cudaGetSymbolAddress(&pQh, g_Qh);   cudaGetSymbolAddress(&pQl, g_Ql);
    cudaGetSymbolAddress(&pKh, g_Kh);

    const uint32_t SMEM_G = 61440;
    cudaFuncSetAttribute(gemm_mma_kernel,
                         cudaFuncAttributeMaxDynamicSharedMemorySize, SMEM_G);

    const int n4x = BS_ * D_ / 4;
    pack_x_kernel<<<n4x / 256, 256>>>(X1, (__half*)pX1p, n4x);
    pack_x_kernel<<<n4x / 256, 256>>>(X2, (__half*)pX2p, n4x);

    const dim3 gT(32, 32), bT(32, 8);
    pack_w_kernel<<<gT, bT>>>(Wq, (__half*)pWqp);
    pack_w_kernel<<<gT, bT>>>(Wk, (__half*)pWkp);
    pack_w_kernel<<<gT, bT>>>(Wv, (__half*)pWvp);
    pack_w_kernel<<<gT, bT>>>(Wo, (__half*)pWop);

    const dim3 gG(HE_ / 128, BS_ / 128);
    // Q projection -> per-head fp16 hi/lo directly
    gemm_mma_kernel<<<gG, 256, SMEM_G>>>((__half*)pX1p, (__half*)pWqp, bq,
                                         nullptr, (__half*)pQh, (__half*)pQl, 1);
    // K projection -> per-head fp16 hi only
    gemm_mma_kernel<<<gG, 256, SMEM_G>>>((__half*)pX2p, (__half*)pWkp, bk,
                                         nullptr, (__half*)pKh, nullptr, 2);
    // V projection -> fp32 (needed by tilesum + transpose)
    gemm_mma_kernel<<<gG, 256, SMEM_G>>>((__half*)pX2p, (__half*)pWvp, bv,
                                         (float*)pV, nullptr, nullptr, 0);

    cvt_vt_kernel<<<dim3(2, 32, B_*H_), dim3(32, 8)>>>();
    tilesum_kernel<<<B_ * H_ * NT_, 64>>>();
    scan_kernel<<<(B_ * H_ * E_) / 256, 256>>>();

    scores_mma_kernel<<<dim3(NT_, NT_, B_ * H_), 128>>>();
    softmax_h_kernel<<<dim3(S_ / 256, S_, B_), 256>>>();
    attnv_mma_kernel<<<dim3(NT_, B_ * H_), 128>>>();

    // output projection straight into d_out
    gemm_mma_kernel<<<gG, 256, SMEM_G>>>((__half*)pAOp, (__half*)pWop, bo,
                                         out, nullptr, nullptr, 0);
}

// round 6
// speedup vs baseline: 2.6080x; 1.0006x over previous
#include <cuda_runtime.h>
#include <cuda_fp16.h>
#include <cstdint>
#include <math.h>

#define B_  8
#define S_  1024
#define D_  1024
#define H_  16
#define E_  64
#define HE_ 1024
#define BS_ (B_*S_)
#define NT_ (S_/64)
#define KP_ 2048          // packed K for projections: [Xh | Xl] x [Wh | Wh]

// ---------------- scratch (device globals; no runtime allocation) ----------
__device__ float g_V [B_*S_*HE_];
__device__ float g_Sc[(size_t)B_*H_*S_*S_];
__device__ float g_TS[B_*H_*NT_*E_];
__device__ float g_P [B_*H_*(NT_+1)*E_];

// packed fp16 operands for projection GEMMs (K folded x2)
__device__ __half g_X1p[(size_t)BS_*KP_];
__device__ __half g_X2p[(size_t)BS_*KP_];
__device__ __half g_AOp[(size_t)BS_*KP_];
__device__ __half g_Wqp[(size_t)HE_*KP_];
__device__ __half g_Wkp[(size_t)HE_*KP_];
__device__ __half g_Wvp[(size_t)HE_*KP_];
__device__ __half g_Wop[(size_t)HE_*KP_];

// per-head fp16 operands for attention mma
__device__ __half g_Qh[(size_t)B_*H_*S_*E_], g_Ql[(size_t)B_*H_*S_*E_];  // [bh][s][e]
__device__ __half g_Kh[(size_t)B_*H_*S_*E_];                             // [bh][s][e]
__device__ __half g_Vth[(size_t)B_*H_*E_*S_];                            // [bh][e][s]
__device__ __half g_Ah[(size_t)B_*H_*S_*S_], g_Al[(size_t)B_*H_*S_*S_];  // [bh][q][k]

// ---------------- PTX helpers (baseline sm_80+) -----------------------------
__device__ __forceinline__ uint32_t smem_u32(const void* p) {
    uint32_t a;
    asm("{ .reg .u64 t; cvta.to.shared.u64 t, %1; cvt.u32.u64 %0, t; }" : "=r"(a) : "l"(p));
    return a;
}
__device__ __forceinline__ void cp16(uint32_t s, const void* g) {
    asm volatile("cp.async.cg.shared.global [%0], [%1], 16;" :: "r"(s), "l"(g));
}
#define CP_COMMIT() asm volatile("cp.async.commit_group;" ::: "memory")
#define CP_WAIT1()  asm volatile("cp.async.wait_group 1;" ::: "memory")
#define CP_WAIT0()  asm volatile("cp.async.wait_group 0;" ::: "memory")

#define LDSM4(r, a) \
    asm volatile("ldmatrix.sync.aligned.m8n8.x4.shared.b16 {%0,%1,%2,%3}, [%4];" \
        : "=r"((r)[0]), "=r"((r)[1]), "=r"((r)[2]), "=r"((r)[3]) : "r"(a))

#define MMAF16(c, a, b0v, b1v) \
    asm volatile("mma.sync.aligned.m16n8k16.row.col.f32.f16.f16.f32 " \
        "{%0,%1,%2,%3}, {%4,%5,%6,%7}, {%8,%9}, {%0,%1,%2,%3};" \
        : "+f"((c)[0]), "+f"((c)[1]), "+f"((c)[2]), "+f"((c)[3]) \
        : "r"((a)[0]), "r"((a)[1]), "r"((a)[2]), "r"((a)[3]), "r"(b0v), "r"(b1v))

// ---------------- pack kernels ---------------------------------------------
// X fp32 [R,1024] -> fp16 [R,2048] as [hi | lo]
__global__ __launch_bounds__(256) void pack_x_kernel(
    const float* __restrict__ in, __half* __restrict__ out, int n4)
{
    int i = blockIdx.x * 256 + threadIdx.x;
    if (i >= n4) return;
    const int row = i >> 8;
    const int c   = (i & 255) * 4;
    float4 v = ((const float4*)in)[i];
    float f[4] = {v.x, v.y, v.z, v.w};
    __half hh[4], ll[4];
    #pragma unroll
    for (int j = 0; j < 4; j++) {
        hh[j] = __float2half_rn(f[j]);
        ll[j] = __float2half_rn(f[j] - __half2float(hh[j]));
    }
    __half* base = out + (size_t)row * KP_;
    *(__half2*)(base + c)          = __half2(hh[0], hh[1]);
    *(__half2*)(base + c + 2)      = __half2(hh[2], hh[3]);
    *(__half2*)(base + 1024 + c)   = __half2(ll[0], ll[1]);
    *(__half2*)(base + 1024 + c+2) = __half2(ll[2], ll[3]);
}

// W fp32 [K=1024, N=1024] -> Wt fp16 [N, 2048] as [hi | hi]
__global__ __launch_bounds__(256) void pack_w_kernel(
    const float* __restrict__ W, __half* __restrict__ out)
{
    __shared__ float t[32][33];
    const int n0 = blockIdx.x * 32, k0 = blockIdx.y * 32;
    const int tx = threadIdx.x, ty = threadIdx.y;
    #pragma unroll
    for (int i = 0; i < 4; i++)
        t[ty + i*8][tx] = W[(size_t)(k0 + ty + i*8) * 1024 + n0 + tx];
    __syncthreads();
    #pragma unroll
    for (int i = 0; i < 4; i++) {
        float v = t[tx][ty + i*8];
        __half h = __float2half_rn(v);
        size_t o = (size_t)(n0 + ty + i*8) * KP_ + k0 + tx;
        out[o]        = h;
        out[o + 1024] = h;
    }
}

// ---------------- projection GEMM (mma.sync fp16, K-fold x2) ---------------
// epilogue modes: 0 = fp32 C row-major; 1 = per-head fp16 hi+lo; 2 = per-head fp16 hi
__global__ __launch_bounds__(256) void gemm_mma_kernel(
    const __half* __restrict__ Ap, const __half* __restrict__ Bp,
    const float* __restrict__ bias, float* __restrict__ C,
    __half* __restrict__ Oh, __half* __restrict__ Ol, int mode)
{
    extern __shared__ char smch[];
    const uint32_t sb = smem_u32(smch);
    const int tid = threadIdx.x;
    const int lane = tid & 31, wid = tid >> 5;
    const int wm = wid >> 2, wn = wid & 3;
    const size_t m0 = (size_t)blockIdx.y * 128;
    const size_t n0 = (size_t)blockIdx.x * 128;

    const int lr = tid >> 2;
    const int lco = (tid & 3) * 16;
    const __half* gA0 = Ap + (m0 + lr) * KP_ + (tid & 3) * 8;
    const __half* gB0 = Bp + (n0 + lr) * KP_ + (tid & 3) * 8;
    const uint32_t smA = sb + lr * 80 + lco;
    const uint32_t smB = smA + 10240;

    float acc[4][4][4];
    #pragma unroll
    for (int a = 0; a < 4; a++)
        #pragma unroll
        for (int b = 0; b < 4; b++)
            #pragma unroll
            for (int c = 0; c < 4; c++) acc[a][b][c] = 0.f;

    #define LOADST(kt, st) do {                                        \
        const uint32_t so_ = (uint32_t)(st) * 20480u;                  \
        const __half* ga_ = gA0 + (kt) * 32;                           \
        const __half* gb_ = gB0 + (kt) * 32;                           \
        cp16(smA + so_,           ga_);                                \
        cp16(smA + so_ + 64*80,   ga_ + (size_t)64 * KP_);             \
        cp16(smB + so_,           gb_);                                \
        cp16(smB + so_ + 64*80,   gb_ + (size_t)64 * KP_);             \
        CP_COMMIT();                                                   \
    } while (0)

    LOADST(0, 0);
    LOADST(1, 1);

    const uint32_t aAddr = sb + (uint32_t)(wm*64 + (lane & 15)) * 80 + ((lane >> 4) << 4);
    const uint32_t bAddr = sb + 10240 +
        (uint32_t)(wn*32 + ((lane >> 3) & 1) * 8 + (lane & 7)) * 80 + ((lane >> 4) << 4);

    const int NKT = KP_ / 32;   // 64
    #pragma unroll 1
    for (int kt = 0; kt < NKT; kt++) {
        const int st = kt % 3;
        CP_WAIT1();
        __syncthreads();
        if (kt + 2 < NKT) LOADST(kt + 2, (kt + 2) % 3);
        const uint32_t so = (uint32_t)st * 20480u;
        #pragma unroll
        for (int ks = 0; ks < 2; ks++) {
            uint32_t afr[4][4], bfr[2][4];
            #pragma unroll
            for (int mt = 0; mt < 4; mt++)
                LDSM4(afr[mt], aAddr + so + (uint32_t)mt*16*80 + ks*32);
            #pragma unroll
            for (int nt2 = 0; nt2 < 2; nt2++)
                LDSM4(bfr[nt2], bAddr + so + (uint32_t)nt2*16*80 + ks*32);
            #pragma unroll
            for (int mt = 0; mt < 4; mt++)
                #pragma unroll
                for (int nt = 0; nt < 4; nt++)
                    MMAF16(acc[mt][nt], afr[mt],
                           bfr[nt >> 1][nt & 1], bfr[nt >> 1][2 + (nt & 1)]);
        }
    }
    CP_WAIT0();

    const int crow = lane >> 2, ccol = (lane & 3) * 2;
    if (mode == 0) {
        #pragma unroll
        for (int nt = 0; nt < 4; nt++) {
            const int n = (int)n0 + wn*32 + nt*8 + ccol;
            const float b0v = bias[n], b1v = bias[n + 1];
            #pragma unroll
            for (int mt = 0; mt < 4; mt++) {
                const size_t m = m0 + wm*64 + mt*16 + crow;
                float2 v0, v1;
                v0.x = acc[mt][nt][0] + b0v; v0.y = acc[mt][nt][1] + b1v;
                v1.x = acc[mt][nt][2] + b0v; v1.y = acc[mt][nt][3] + b1v;
                *(float2*)(C + m * 1024 + n)       = v0;
                *(float2*)(C + (m + 8) * 1024 + n) = v1;
            }
        }
    } else {
        #pragma unroll
        for (int nt = 0; nt < 4; nt++) {
            const int n = (int)n0 + wn*32 + nt*8 + ccol;
            const float b0v = bias[n], b1v = bias[n + 1];
            const int h = n >> 6, e = n & 63;
            #pragma unroll
            for (int mt = 0; mt < 4; mt++) {
                #pragma unroll
                for (int half = 0; half < 2; half++) {
                    const size_t m = m0 + wm*64 + mt*16 + crow + half*8;
                    const int b2 = (int)(m >> 10), s = (int)(m & 1023);
                    const size_t o = (((size_t)(b2*16 + h) * 1024 + s) * 64 + e);
                    const float v0 = acc[mt][nt][half*2]     + b0v;
                    const float v1 = acc[mt][nt][half*2 + 1] + b1v;
                    const __half h0 = __float2half_rn(v0);
                    const __half h1 = __float2half_rn(v1);
                    *(__half2*)(Oh + o) = __half2(h0, h1);
                    if (mode == 1) {
                        const __half l0 = __float2half_rn(v0 - __half2float(h0));
                        const __half l1 = __float2half_rn(v1 - __half2float(h1));
                        *(__half2*)(Ol + o) = __half2(l0, l1);
                    }
                }
            }
        }
    }
    #undef LOADST
}

// ---------------- V fp32 -> transposed per-head fp16 hi --------------------
__global__ void cvt_vt_kernel()
{
    __shared__ float t[32][33];
    const int bh = blockIdx.z;
    const int b = bh >> 4, h = bh & 15;
    const int s0 = blockIdx.y * 32, e0 = blockIdx.x * 32;
    const int tx = threadIdx.x, ty = threadIdx.y;
    #pragma unroll
    for (int i = 0; i < 4; i++)
        t[ty + i*8][tx] = g_V[((size_t)(b*1024) + s0 + ty + i*8) * 1024 + h*64 + e0 + tx];
    __syncthreads();
    #pragma unroll
    for (int i = 0; i < 4; i++) {
        const float v = t[tx][ty + i*8];
        g_Vth[((size_t)bh * 64 + e0 + ty + i*8) * 1024 + s0 + tx] = __float2half_rn(v);
    }
}

// ---------------- scores via mma (fp16 x2), quirks fused -------------------
// grid (kt, qt, bh), block 128 (4 warps, 2x2 of 32x32)
__global__ __launch_bounds__(128) void scores_mma_kernel()
{
    const int kt = blockIdx.x, qt = blockIdx.y;
    if (kt > qt) return;
    const int bh = blockIdx.z;

    __shared__ __align__(16) char sm[3 * 64 * 144];
    const uint32_t sQH = smem_u32(sm);
    const uint32_t sQL = sQH +  9216;
    const uint32_t sKH = sQH + 18432;

    const int tid = threadIdx.x;
    const int lane = tid & 31, wid = tid >> 5;
    const int wm = wid >> 1, wn = wid & 1;

    const __half* gQH = g_Qh + ((size_t)bh * 1024 + qt*64) * 64;
    const __half* gQL = g_Ql + ((size_t)bh * 1024 + qt*64) * 64;
    const __half* gKH = g_Kh + ((size_t)bh * 1024 + kt*64) * 64;
    #pragma unroll
    for (int i = tid; i < 512; i += 128) {
        const int r = i >> 3, c = i & 7;
        const size_t go = (size_t)r * 64 + c * 8;
        const uint32_t so = r * 144 + c * 16;
        *(uint4*)(sm + so)         = *(const uint4*)(gQH + go);
        *(uint4*)(sm + 9216 + so)  = *(const uint4*)(gQL + go);
        *(uint4*)(sm + 18432 + so) = *(const uint4*)(gKH + go);
    }
    __syncthreads();

    float acc[2][4][4];
    #pragma unroll
    for (int a = 0; a < 2; a++)
        #pragma unroll
        for (int b2 = 0; b2 < 4; b2++)
            #pragma unroll
            for (int c = 0; c < 4; c++) acc[a][b2][c] = 0.f;

    const uint32_t aOff = (uint32_t)(wm*32 + (lane & 15)) * 144 + ((lane >> 4) << 4);
    const uint32_t bOff = (uint32_t)(wn*32 + ((lane >> 3) & 1)*8 + (lane & 7)) * 144 + ((lane >> 4) << 4);

    #pragma unroll
    for (int es = 0; es < 4; es++) {
        const uint32_t cb = es * 32;
        uint32_t ah[2][4], al[2][4], bh2[2][4];
        #pragma unroll
        for (int mt = 0; mt < 2; mt++) {
            LDSM4(ah[mt], sQH + aOff + (uint32_t)mt*16*144 + cb);
            LDSM4(al[mt], sQL + aOff + (uint32_t)mt*16*144 + cb);
        }
        #pragma unroll
        for (int nt2 = 0; nt2 < 2; nt2++)
            LDSM4(bh2[nt2], sKH + bOff + (uint32_t)nt2*16*144 + cb);
        #pragma unroll
        for (int mt = 0; mt < 2; mt++)
            #pragma unroll
            for (int nt = 0; nt < 4; nt++) {
                MMAF16(acc[mt][nt], ah[mt], bh2[nt>>1][nt&1], bh2[nt>>1][2+(nt&1)]);
                MMAF16(acc[mt][nt], al[mt], bh2[nt>>1][nt&1], bh2[nt>>1][2+(nt&1)]);
            }
    }

    const float scale = 0.35355339059327373f;  // 1/sqrt(8) batch-size quirk
    float* out = g_Sc + (size_t)bh * S_ * S_;
    #pragma unroll
    for (int mt = 0; mt < 2; mt++) {
        #pragma unroll
        for (int half = 0; half < 2; half++) {
            const int q = qt*64 + wm*32 + mt*16 + (lane >> 2) + half*8;
            #pragma unroll
            for (int nt = 0; nt < 4; nt++) {
                const int k0 = kt*64 + wn*32 + nt*8 + (lane & 3)*2;
                float v0 = acc[mt][nt][half*2]     * scale;
                float v1 = acc[mt][nt][half*2 + 1] * scale;
                if (k0     > q || v0 == 0.0f) v0 = -1e9f;
                if (k0 + 1 > q || v1 == 0.0f) v1 = -1e9f;
                *(float2*)(out + (size_t)q * S_ + k0) = make_float2(v0, v1);
            }
        }
    }
}

// ---------------- softmax over heads -> fp16 hi/lo attn --------------------
__global__ void softmax_h_kernel()
{
    const int k = blockIdx.x * 256 + threadIdx.x;
    const int q = blockIdx.y;
    const int b = blockIdx.z;
    const int kmax = ((q >> 6) + 1) << 6;
    if (k >= kmax) return;

    const size_t base = (size_t)b * H_ * S_ * S_ + (size_t)q * S_ + k;
    const size_t hs   = (size_t)S_ * S_;
    float s[H_];
    float m = -3.4e38f;
    #pragma unroll
    for (int h = 0; h < H_; h++) { s[h] = g_Sc[base + h * hs]; m = fmaxf(m, s[h]); }
    float Z = 0.f;
    #pragma unroll
    for (int h = 0; h < H_; h++) { s[h] = expf(s[h] - m); Z += s[h]; }
    const float inv = 1.0f / Z;
    #pragma unroll
    for (int h = 0; h < H_; h++) {
        const float a = s[h] * inv;
        const __half ah = __float2half_rn(a);
        g_Ah[base + h * hs] = ah;
        g_Al[base + h * hs] = __float2half_rn(a - __half2float(ah));
    }
}

// ---------------- V tile sums + prefix scan --------------------------------
__global__ void tilesum_kernel()
{
    const int blk = blockIdx.x;
    const int e = threadIdx.x;
    const int tt = blk & (NT_ - 1);
    const int bh = blk / NT_;
    const int b = bh >> 4, h = bh & 15;
    const float* Vb = g_V + ((size_t)(b*S_ + tt*64)) * HE_ + h*64 + e;
    float sum = 0.f;
    #pragma unroll 8
    for (int k = 0; k < 64; k++) sum += Vb[(size_t)k * HE_];
    g_TS[((size_t)bh * NT_ + tt) * E_ + e] = sum;
}

__global__ void scan_kernel()
{
    const int id = blockIdx.x * 256 + threadIdx.x;
    const int e = id & 63, bh = id >> 6;
    float* P = g_P + (size_t)bh * (NT_ + 1) * E_;
    float p = 0.f;
    P[e] = 0.f;
    #pragma unroll
    for (int tt = 0; tt < NT_; tt++) {
        p += g_TS[((size_t)bh * NT_ + tt) * E_ + e];
        P[(tt + 1) * E_ + e] = p;
    }
}

// ---------------- attn @ V via mma (fp16 x2) + masked suffix ---------------
// grid (qt, bh), block 128; epilogue writes PACKED fold-2048 AO operand
__global__ __launch_bounds__(128) void attnv_mma_kernel()
{
    const int qt = blockIdx.x, bh = blockIdx.y;
    const int b = bh >> 4, h = bh & 15;

    __shared__ __align__(16) char sm[3 * 64 * 144];
    const uint32_t sAH = smem_u32(sm);
    const uint32_t sAL = sAH +  9216;
    const uint32_t sVH = sAH + 18432;

    const int tid = threadIdx.x;
    const int lane = tid & 31, wid = tid >> 5;
    const int wm = wid >> 1, wn = wid & 1;

    float acc[2][4][4];
    #pragma unroll
    for (int a = 0; a < 2; a++)
        #pragma unroll
        for (int b2 = 0; b2 < 4; b2++)
            #pragma unroll
            for (int c = 0; c < 4; c++) acc[a][b2][c] = 0.f;

    const uint32_t aOff = (uint32_t)(wm*32 + (lane & 15)) * 144 + ((lane >> 4) << 4);
    const uint32_t bOff = (uint32_t)(wn*32 + ((lane >> 3) & 1)*8 + (lane & 7)) * 144 + ((lane >> 4) << 4);

    const __half* gAH0 = g_Ah + ((size_t)bh * 1024 + qt*64) * 1024;
    const __half* gAL0 = g_Al + ((size_t)bh * 1024 + qt*64) * 1024;
    const __half* gVH0 = g_Vth + (size_t)bh * 64 * 1024;

    for (int kt = 0; kt <= qt; kt++) {
        __syncthreads();
        #pragma unroll
        for (int i = tid; i < 512; i += 128) {
            const int r = i >> 3, c = i & 7;
            const size_t go = (size_t)r * 1024 + kt*64 + c * 8;
            const uint32_t so = r * 144 + c * 16;
            *(uint4*)(sm + so)         = *(const uint4*)(gAH0 + go);
            *(uint4*)(sm + 9216 + so)  = *(const uint4*)(gAL0 + go);
            *(uint4*)(sm + 18432 + so) = *(const uint4*)(gVH0 + go);
        }
        __syncthreads();

        #pragma unroll
        for (int ks = 0; ks < 4; ks++) {
            const uint32_t cb = ks * 32;
            uint32_t ah[2][4], al[2][4], vh[2][4];
            #pragma unroll
            for (int mt = 0; mt < 2; mt++) {
                LDSM4(ah[mt], sAH + aOff + (uint32_t)mt*16*144 + cb);
                LDSM4(al[mt], sAL + aOff + (uint32_t)mt*16*144 + cb);
            }
            #pragma unroll
            for (int nt2 = 0; nt2 < 2; nt2++)
                LDSM4(vh[nt2], sVH + bOff + (uint32_t)nt2*16*144 + cb);
            #pragma unroll
            for (int mt = 0; mt < 2; mt++)
                #pragma unroll
                for (int nt = 0; nt < 4; nt++) {
                    MMAF16(acc[mt][nt], ah[mt], vh[nt>>1][nt&1], vh[nt>>1][2+(nt&1)]);
                    MMAF16(acc[mt][nt], al[mt], vh[nt>>1][nt&1], vh[nt>>1][2+(nt&1)]);
                }
        }
    }

    // masked suffix: attn = 1/16 exactly for k beyond causal band; then write
    // packed [hi | lo] fold-2048 operand for the output projection GEMM.
    const float* P = g_P + (size_t)bh * (NT_ + 1) * E_;
    #pragma unroll
    for (int nt = 0; nt < 4; nt++) {
        const int e0 = wn*32 + nt*8 + (lane & 3)*2;
        const float s0 = (P[NT_*E_ + e0]     - P[(qt+1)*E_ + e0])     * 0.0625f;
        const float s1 = (P[NT_*E_ + e0 + 1] - P[(qt+1)*E_ + e0 + 1]) * 0.0625f;
        #pragma unroll
        for (int mt = 0; mt < 2; mt++) {
            #pragma unroll
            for (int half = 0; half < 2; half++) {
                const int q = wm*32 + mt*16 + (lane >> 2) + half*8;
                const float v0 = acc[mt][nt][half*2]     + s0;
                const float v1 = acc[mt][nt][half*2 + 1] + s1;
                const __half h0 = __float2half_rn(v0);
                const __half h1 = __float2half_rn(v1);
                const __half l0 = __float2half_rn(v0 - __half2float(h0));
                const __half l1 = __float2half_rn(v1 - __half2float(h1));
                __half* base = g_AOp + ((size_t)(b*1024 + qt*64 + q)) * KP_ + h*64 + e0;
                *(__half2*)(base)        = __half2(h0, h1);
                *(__half2*)(base + 1024) = __half2(l0, l1);
            }
        }
    }
}

// ---------------- launch ---------------------------------------------------
extern "C" void kernel_launch(void* const* d_in, const int* in_sizes, int n_in,
                              void* d_out, int out_size)
{
    const float* X1 = (const float*)d_in[0];
    const float* X2 = (const float*)d_in[1];
    const float* Wq = (const float*)d_in[2];
    const float* bq = (const float*)d_in[3];
    const float* Wk = (const float*)d_in[4];
    const float* bk = (const float*)d_in[5];
    const float* Wv = (const float*)d_in[6];
    const float* bv = (const float*)d_in[7];
    const float* Wo = (const float*)d_in[8];
    const float* bo = (const float*)d_in[9];
    float* out = (float*)d_out;

    void *pV;
    void *pX1p, *pX2p, *pAOp, *pWqp, *pWkp, *pWvp, *pWop;
    void *pQh, *pQl, *pKh;
    cudaGetSymbolAddress(&pV,  g_V);
    cudaGetSymbolAddress(&pX1p, g_X1p); cudaGetSymbolAddress(&pX2p, g_X2p);
    cudaGetSymbolAddress(&pAOp, g_AOp);
    cudaGetSymbolAddress(&pWqp, g_Wqp); cudaGetSymbolAddress(&pWkp, g_Wkp);
    cudaGetSymbolAddress(&pWvp, g_Wvp); cudaGetSymbolAddress(&pWop, g_Wop);
    cudaGetSymbolAddress(&pQh, g_Qh);   cudaGetSymbolAddress(&pQl, g_Ql);
    cudaGetSymbolAddress(&pKh, g_Kh);

    const uint32_t SMEM_G = 61440;
    cudaFuncSetAttribute(gemm_mma_kernel,
                         cudaFuncAttributeMaxDynamicSharedMemorySize, SMEM_G);

    const int n4x = BS_ * D_ / 4;
    pack_x_kernel<<<n4x / 256, 256>>>(X1, (__half*)pX1p, n4x);
    pack_x_kernel<<<n4x / 256, 256>>>(X2, (__half*)pX2p, n4x);

    const dim3 gT(32, 32), bT(32, 8);
    pack_w_kernel<<<gT, bT>>>(Wq, (__half*)pWqp);
    pack_w_kernel<<<gT, bT>>>(Wk, (__half*)pWkp);
    pack_w_kernel<<<gT, bT>>>(Wv, (__half*)pWvp);
    pack_w_kernel<<<gT, bT>>>(Wo, (__half*)pWop);

    const dim3 gG(HE_ / 128, BS_ / 128);
    // Q projection -> per-head fp16 hi/lo directly
    gemm_mma_kernel<<<gG, 256, SMEM_G>>>((__half*)pX1p, (__half*)pWqp, bq,
                                         nullptr, (__half*)pQh, (__half*)pQl, 1);
    // K projection -> per-head fp16 hi only
    gemm_mma_kernel<<<gG, 256, SMEM_G>>>((__half*)pX2p, (__half*)pWkp, bk,
                                         nullptr, (__half*)pKh, nullptr, 2);
    // V projection -> fp32 (needed by tilesum + transpose)
    gemm_mma_kernel<<<gG, 256, SMEM_G>>>((__half*)pX2p, (__half*)pWvp, bv,
                                         (float*)pV, nullptr, nullptr, 0);

    cvt_vt_kernel<<<dim3(2, 32, B_*H_), dim3(32, 8)>>>();
    tilesum_kernel<<<B_ * H_ * NT_, 64>>>();
    scan_kernel<<<(B_ * H_ * E_) / 256, 256>>>();

    scores_mma_kernel<<<dim3(NT_, NT_, B_ * H_), 128>>>();
    softmax_h_kernel<<<dim3(S_ / 256, S_, B_), 256>>>();
    attnv_mma_kernel<<<dim3(NT_, B_ * H_), 128>>>();

    // output projection straight into d_out
    gemm_mma_kernel<<<gG, 256, SMEM_G>>>((__half*)pAOp, (__half*)pWop, bo,
                                         out, nullptr, nullptr, 0);
}